// round 15
// baseline (speedup 1.0000x reference)
#include <cuda_runtime.h>
#include <cuda_fp16.h>
#include <cstdint>

#define N_NODES 50000
#define N_EDGES 800000
#define N_GRAPHS 1024
#define NLAYERS 5
#define TEDG 32
#define N_UNITS (N_EDGES / TEDG)   // 25000
#define SCAN_NB 98                 // ceil(50000/512)

// ---------------- scratch (device globals; no allocation allowed) ----------------
__device__ __align__(16) float  g_x[N_NODES * 128];
__device__ __align__(16) __half g_xh[N_NODES * 128];
__device__ __align__(16) __half g_eh[N_EDGES * 128];     // dst-sorted edge features
__device__ __align__(16) __half g_xw[N_NODES * 256];     // fp16 XW = x@W1a + b1
__device__ __align__(16) float  g_aggr[N_NODES * 128];
__device__ __align__(16) float  g_pool[N_GRAPHS * 128];
__device__ __align__(16) float  g_gcnt[N_GRAPHS];
__device__ __align__(16) uint2  g_w1p[NLAYERS * 8192];   // W1b fragment-packed
__device__ __align__(16) uint2  g_w2p[NLAYERS * 8192];   // W2 fragment-packed
__device__ __align__(16) uint2  g_ewp[1536];             // edge_w fragment-packed
__device__ int g_deg[N_NODES];
__device__ int g_cur[N_NODES];
__device__ int g_off[N_NODES];
__device__ int g_bsum[SCAN_NB];
__device__ int g_pos[N_EDGES];
__device__ int g_srcs[N_EDGES];
__device__ int g_dsts[N_EDGES];

// silu via tanh.approx: sigma(x) = 0.5 + 0.5*tanh(x/2); 1 MUFU + FMA-pipe ops
__device__ __forceinline__ float silu_f(float v) {
    float t;
    asm("tanh.approx.f32 %0, %1;" : "=f"(t) : "f"(0.5f * v));
    return v * fmaf(t, 0.5f, 0.5f);
}

__device__ __forceinline__ uint32_t sptr(const void* p) {
    return (uint32_t)__cvta_generic_to_shared(p);
}
__device__ __forceinline__ uint32_t swz(int row, int c8, int rowBytes) {
    return (uint32_t)(row * rowBytes + (((c8 ^ (row & 7)) << 4)));
}
__device__ __forceinline__ void ldsm_x4(uint32_t* r, uint32_t addr) {
    asm volatile("ldmatrix.sync.aligned.m8n8.x4.shared.b16 {%0,%1,%2,%3}, [%4];\n"
                 : "=r"(r[0]), "=r"(r[1]), "=r"(r[2]), "=r"(r[3]) : "r"(addr));
}
__device__ __forceinline__ void ldsm_x4_t(uint32_t* r, uint32_t addr) {
    asm volatile("ldmatrix.sync.aligned.m8n8.x4.trans.shared.b16 {%0,%1,%2,%3}, [%4];\n"
                 : "=r"(r[0]), "=r"(r[1]), "=r"(r[2]), "=r"(r[3]) : "r"(addr));
}
__device__ __forceinline__ void mma_16816(float* c, const uint32_t* a, const uint32_t* b) {
    asm volatile(
        "mma.sync.aligned.m16n8k16.row.col.f32.f16.f16.f32 "
        "{%0,%1,%2,%3}, {%4,%5,%6,%7}, {%8,%9}, {%0,%1,%2,%3};\n"
        : "+f"(c[0]), "+f"(c[1]), "+f"(c[2]), "+f"(c[3])
        : "r"(a[0]), "r"(a[1]), "r"(a[2]), "r"(a[3]), "r"(b[0]), "r"(b[1]));
}
__device__ __forceinline__ void red2(float* p, float a, float b) {
    asm volatile("red.global.add.v2.f32 [%0], {%1,%2};" :: "l"(p), "f"(a), "f"(b) : "memory");
}
#define CP_ASYNC16(sdst, gsrc) \
    asm volatile("cp.async.cg.shared.global [%0], [%1], 16;" :: "r"(sdst), "l"(gsrc) : "memory")
#define CP_COMMIT() asm volatile("cp.async.commit_group;" ::: "memory")
#define CP_WAIT0()  asm volatile("cp.async.wait_group 0;" ::: "memory")

// ---------------- node embedding (warp-per-node) ----------------
__global__ __launch_bounds__(128) void k_node_embed(
    const float* __restrict__ atom, const float* __restrict__ w,
    const float* __restrict__ b, const float* __restrict__ lg,
    const float* __restrict__ lb, float* __restrict__ x, __half* __restrict__ xh)
{
    const int lane = threadIdx.x & 31, wp = threadIdx.x >> 5;
    const long n = (long)blockIdx.x * 4 + wp;
    const int c0 = lane * 4;
    float4 a = *(const float4*)(atom + n * 4);
    float v[4];
    #pragma unroll
    for (int c = 0; c < 4; c++) {
        int col = c0 + c;
        float acc = __ldg(&b[col]);
        acc = fmaf(a.x, __ldg(&w[0 * 128 + col]), acc);
        acc = fmaf(a.y, __ldg(&w[1 * 128 + col]), acc);
        acc = fmaf(a.z, __ldg(&w[2 * 128 + col]), acc);
        acc = fmaf(a.w, __ldg(&w[3 * 128 + col]), acc);
        v[c] = acc;
    }
    float s = v[0] + v[1] + v[2] + v[3];
    float s2 = v[0] * v[0] + v[1] * v[1] + v[2] * v[2] + v[3] * v[3];
    #pragma unroll
    for (int o = 16; o > 0; o >>= 1) {
        s  += __shfl_xor_sync(0xffffffffu, s,  o);
        s2 += __shfl_xor_sync(0xffffffffu, s2, o);
    }
    float mean = s * (1.0f / 128.0f);
    float var  = s2 * (1.0f / 128.0f) - mean * mean;
    float rstd = rsqrtf(var + 1e-5f);
    float4 gv = *(const float4*)(lg + c0);
    float4 bv = *(const float4*)(lb + c0);
    float o0 = silu_f((v[0] - mean) * rstd * gv.x + bv.x);
    float o1 = silu_f((v[1] - mean) * rstd * gv.y + bv.y);
    float o2 = silu_f((v[2] - mean) * rstd * gv.z + bv.z);
    float o3 = silu_f((v[3] - mean) * rstd * gv.w + bv.w);
    *(float4*)(x + n * 128 + c0) = make_float4(o0, o1, o2, o3);
    __half2 h0 = __floats2half2_rn(o0, o1);
    __half2 h1 = __floats2half2_rn(o2, o3);
    *(uint2*)(xh + n * 128 + c0) = make_uint2(*(uint32_t*)&h0, *(uint32_t*)&h1);
}

// ---------------- degree count ----------------
__global__ void k_deg(const int* __restrict__ idx, int* __restrict__ deg, int nE) {
    int i = blockIdx.x * blockDim.x + threadIdx.x;
    if (i < nE) atomicAdd(&deg[idx[2 * i + 1]], 1);
}

// ---------------- parallel exclusive scan (3 kernels) ----------------
__global__ __launch_bounds__(512) void k_scan1(const int* __restrict__ deg,
                                               int* __restrict__ bsum)
{
    __shared__ int ws[16];
    int tid = threadIdx.x, lane = tid & 31, w = tid >> 5;
    int i = blockIdx.x * 512 + tid;
    int v = (i < N_NODES) ? deg[i] : 0;
    int s = v;
    #pragma unroll
    for (int o = 16; o > 0; o >>= 1) s += __shfl_xor_sync(0xffffffffu, s, o);
    if (lane == 0) ws[w] = s;
    __syncthreads();
    if (tid == 0) {
        int tot = 0;
        #pragma unroll
        for (int j = 0; j < 16; j++) tot += ws[j];
        bsum[blockIdx.x] = tot;
    }
}

__global__ __launch_bounds__(128) void k_scan2(int* __restrict__ bsum)
{
    __shared__ int ws[4];
    int tid = threadIdx.x, lane = tid & 31, w = tid >> 5;
    int v = (tid < SCAN_NB) ? bsum[tid] : 0;
    int incl = v;
    #pragma unroll
    for (int o = 1; o < 32; o <<= 1) {
        int t2 = __shfl_up_sync(0xffffffffu, incl, o);
        if (lane >= o) incl += t2;
    }
    if (lane == 31) ws[w] = incl;
    __syncthreads();
    int add = 0;
    for (int j = 0; j < w; j++) add += ws[j];
    incl += add;
    if (tid < SCAN_NB) bsum[tid] = incl - v;   // exclusive
}

__global__ __launch_bounds__(512) void k_scan3(const int* __restrict__ deg,
                                               const int* __restrict__ bsum,
                                               int* __restrict__ off)
{
    __shared__ int ws[16];
    int tid = threadIdx.x, lane = tid & 31, w = tid >> 5;
    int i = blockIdx.x * 512 + tid;
    int v = (i < N_NODES) ? deg[i] : 0;
    int incl = v;
    #pragma unroll
    for (int o = 1; o < 32; o <<= 1) {
        int t2 = __shfl_up_sync(0xffffffffu, incl, o);
        if (lane >= o) incl += t2;
    }
    if (lane == 31) ws[w] = incl;
    __syncthreads();
    int add = 0;
    for (int j = 0; j < w; j++) add += ws[j];
    if (i < N_NODES) off[i] = incl - v + add + bsum[blockIdx.x];
}

// ---------------- edge scatter (counting sort by dst) ----------------
__global__ void k_scatter(const int* __restrict__ nbr, const int* __restrict__ off,
                          int* __restrict__ cur, int* __restrict__ pos,
                          int* __restrict__ srcs, int* __restrict__ dsts)
{
    int i = blockIdx.x * blockDim.x + threadIdx.x;
    if (i < N_EDGES) {
        int d = nbr[2 * i + 1];
        int p = off[d] + atomicAdd(&cur[d], 1);
        pos[i] = p;
        srcs[p] = nbr[2 * i];
        dsts[p] = d;
    }
}

// ---------------- weight fragment packing ----------------
__global__ __launch_bounds__(256) void k_cvt(
    const float* __restrict__ w1, const float* __restrict__ w2,
    const float* __restrict__ ew,
    uint2* __restrict__ w1p, uint2* __restrict__ w2p, uint2* __restrict__ ewp)
{
    int i = blockIdx.x * 256 + threadIdx.x;
    if (i >= NLAYERS * 8192) return;
    int lane = i & 31;
    int t = lane & 3, g = lane >> 2;
    {   // W1P
        int r = i >> 5;
        int nt = r & 31; r >>= 5;
        int ks = r & 7;  int layer = r >> 3;
        const float* W = w1 + (long)layer * 65536;
        int n = nt * 8 + g, k0 = ks * 16 + 2 * t;
        __half2 a = __floats2half2_rn(W[(128 + k0) * 256 + n], W[(129 + k0) * 256 + n]);
        __half2 b = __floats2half2_rn(W[(136 + k0) * 256 + n], W[(137 + k0) * 256 + n]);
        w1p[i] = make_uint2(*(uint32_t*)&a, *(uint32_t*)&b);
    }
    {   // W2P
        int r = i >> 5;
        int nt = r & 15; r >>= 4;
        int ks = r & 15; int layer = r >> 4;
        const float* W = w2 + (long)layer * 32768;
        int n = nt * 8 + g, k0 = ks * 16 + 2 * t;
        __half2 a = __floats2half2_rn(W[k0 * 128 + n],       W[(k0 + 1) * 128 + n]);
        __half2 b = __floats2half2_rn(W[(k0 + 8) * 128 + n], W[(k0 + 9) * 128 + n]);
        w2p[i] = make_uint2(*(uint32_t*)&a, *(uint32_t*)&b);
    }
    if (i < 1536) {   // EWP
        int r = i >> 5;
        int nt = r & 15;
        int ks = r >> 4;
        int n = nt * 8 + g, k0 = ks * 16 + 2 * t;
        float v0 = (k0     < 41) ? ew[(k0    ) * 128 + n] : 0.0f;
        float v1 = (k0 + 1 < 41) ? ew[(k0 + 1) * 128 + n] : 0.0f;
        float v2 = (k0 + 8 < 41) ? ew[(k0 + 8) * 128 + n] : 0.0f;
        float v3 = (k0 + 9 < 41) ? ew[(k0 + 9) * 128 + n] : 0.0f;
        __half2 a = __floats2half2_rn(v0, v1);
        __half2 b = __floats2half2_rn(v2, v3);
        ewp[i] = make_uint2(*(uint32_t*)&a, *(uint32_t*)&b);
    }
}

// ---------------- edge embedding (HMMA) ----------------
__global__ __launch_bounds__(256) void k_edge_embed(
    const float* __restrict__ nbr, const uint2* __restrict__ EWP,
    const float* __restrict__ b, const int* __restrict__ pos, __half* __restrict__ e)
{
    __shared__ __align__(16) char sA[64 * 128];
    __shared__ int spos[64];
    const int tid = threadIdx.x, lane = tid & 31, warp = tid >> 5;
    const int wm = (warp & 3) * 16, wnh = warp >> 2;
    const int g = lane >> 2, t = lane & 3;
    const uint32_t sbase = sptr(sA);
    const long e0 = (long)blockIdx.x * 64;

    if (tid < 64) spos[tid] = __ldg(&pos[e0 + tid]);
    #pragma unroll
    for (int p = 0; p < 16; p++) {
        int i = tid + p * 256;
        int row = i >> 6, c = i & 63;
        float v = (c < 41) ? __ldg(&nbr[(e0 + row) * 41 + c]) : 0.0f;
        __half hv = __float2half_rn(v);
        *(__half*)(sA + swz(row, c >> 3, 128) + ((c & 7) << 1)) = hv;
    }
    __syncthreads();

    float acc[8][4];
    #pragma unroll
    for (int nj = 0; nj < 8; nj++)
        #pragma unroll
        for (int q = 0; q < 4; q++) acc[nj][q] = 0.0f;

    #pragma unroll
    for (int ks = 0; ks < 3; ks++) {
        uint32_t af[4];
        ldsm_x4(af, sbase + swz(wm + (lane & 15), ks * 2 + (lane >> 4), 128));
        uint2 bf[8];
        const uint2* bp = EWP + (ks * 16 + wnh * 8) * 32 + lane;
        #pragma unroll
        for (int nj = 0; nj < 8; nj++) bf[nj] = __ldg(bp + nj * 32);
        #pragma unroll
        for (int nj = 0; nj < 8; nj++)
            mma_16816(acc[nj], af, (uint32_t*)&bf[nj]);
    }

    int r0 = wm + g, r1 = r0 + 8;
    long p0 = spos[r0], p1 = spos[r1];
    #pragma unroll
    for (int nj = 0; nj < 8; nj++) {
        int col = wnh * 64 + nj * 8 + 2 * t;
        float2 bb = __ldg((const float2*)(b + col));
        __half2 h0 = __floats2half2_rn(silu_f(acc[nj][0] + bb.x),
                                       silu_f(acc[nj][1] + bb.y));
        __half2 h1 = __floats2half2_rn(silu_f(acc[nj][2] + bb.x),
                                       silu_f(acc[nj][3] + bb.y));
        *(uint32_t*)(e + p0 * 128 + col) = *(uint32_t*)&h0;
        *(uint32_t*)(e + p1 * 128 + col) = *(uint32_t*)&h1;
    }
}

// ================= k_xw family =================
#define XW_SE 0
#define XW_SW 32768
#define XW_SMEM 98304

template <int KR, int NC>
__device__ __forceinline__ void wload(char* sdst, const float* __restrict__ W, int tid) {
    const float4* wv = (const float4*)W;
    constexpr int NV = NC / 4;
    #pragma unroll 4
    for (int i = tid; i < KR * NV; i += 512) {
        int k = i / NV, n4 = (i % NV) * 4;
        float4 v = __ldg(&wv[i]);
        __half2 a = __floats2half2_rn(v.x, v.y);
        __half2 b = __floats2half2_rn(v.z, v.w);
        char* p = sdst + swz(k, n4 >> 3, NC * 2) + ((n4 & 7) << 1);
        *(uint32_t*)p = *(uint32_t*)&a;
        *(uint32_t*)(p + 4) = *(uint32_t*)&b;
    }
}

// shared GEMM tail: A tile + W staged in smem -> XW (fp16)
__device__ __forceinline__ void xw_gemm_tail(
    char* sm, uint32_t sbase, const float* __restrict__ b1,
    __half* __restrict__ XW, long rowBase)
{
    const int tid = threadIdx.x, lane = tid & 31, warp = tid >> 5;
    const int wm = (warp & 3) * 32, wn = warp >> 2;
    const int g = lane >> 2, t = lane & 3;

    float acc[2][8][4];
    #pragma unroll
    for (int mi = 0; mi < 2; mi++)
        #pragma unroll
        for (int nj = 0; nj < 8; nj++)
            #pragma unroll
            for (int q = 0; q < 4; q++) acc[mi][nj][q] = 0.0f;

    for (int ks = 0; ks < 8; ks++) {
        uint32_t af[2][4], bf[8][2];
        #pragma unroll
        for (int mi = 0; mi < 2; mi++)
            ldsm_x4(af[mi], sbase + XW_SE +
                    swz(wm + mi * 16 + (lane & 15), ks * 2 + (lane >> 4), 256));
        #pragma unroll
        for (int np = 0; np < 4; np++) {
            uint32_t r4[4];
            ldsm_x4_t(r4, sbase + XW_SW +
                      swz(ks * 16 + (lane & 15), wn * 8 + np * 2 + (lane >> 4), 512));
            bf[np * 2 + 0][0] = r4[0]; bf[np * 2 + 0][1] = r4[1];
            bf[np * 2 + 1][0] = r4[2]; bf[np * 2 + 1][1] = r4[3];
        }
        #pragma unroll
        for (int mi = 0; mi < 2; mi++)
            #pragma unroll
            for (int nj = 0; nj < 8; nj++)
                mma_16816(acc[mi][nj], af[mi], bf[nj]);
    }

    #pragma unroll
    for (int mi = 0; mi < 2; mi++) {
        long g0 = rowBase + wm + mi * 16 + g, g1 = g0 + 8;
        #pragma unroll
        for (int nj = 0; nj < 8; nj++) {
            int col = wn * 64 + nj * 8 + 2 * t;
            float2 bb = *(const float2*)(b1 + col);
            if (g0 < N_NODES) {
                __half2 h = __floats2half2_rn(acc[mi][nj][0] + bb.x, acc[mi][nj][1] + bb.y);
                *(uint32_t*)(XW + g0 * 256 + col) = *(uint32_t*)&h;
            }
            if (g1 < N_NODES) {
                __half2 h = __floats2half2_rn(acc[mi][nj][2] + bb.x, acc[mi][nj][3] + bb.y);
                *(uint32_t*)(XW + g1 * 256 + col) = *(uint32_t*)&h;
            }
        }
    }
}

// layer-0 k_xw: A tile from precomputed xh
__global__ __launch_bounds__(512) void k_xw(
    const __half* __restrict__ Xh, const float* __restrict__ W1a,
    const float* __restrict__ b1, __half* __restrict__ XW)
{
    extern __shared__ char sm[];
    const int tid = threadIdx.x;
    const uint32_t sbase = sptr(sm);
    const long rowBase = (long)blockIdx.x * 128;

    wload<128, 256>(sm + XW_SW, W1a, tid);
    {
        int row = tid >> 2, cb = (tid & 3) * 4;
        long grow = rowBase + row;
        if (grow >= N_NODES) grow = N_NODES - 1;
        const uint4* p = (const uint4*)(Xh + grow * 128) + cb;
        #pragma unroll
        for (int j = 0; j < 4; j++)
            *(uint4*)(sm + XW_SE + swz(row, cb + j, 256)) = __ldg(p + j);
    }
    __syncthreads();
    xw_gemm_tail(sm, sbase, b1, XW, rowBase);
}

// layers 1..4: fused LN(x + aggr/deg) -> x, zero aggr, stage A, GEMM
__global__ __launch_bounds__(512) void k_xw_ln(
    const float* __restrict__ lg, const float* __restrict__ lb,
    const int* __restrict__ deg, float* __restrict__ x, float* __restrict__ aggr,
    const float* __restrict__ W1a, const float* __restrict__ b1,
    __half* __restrict__ XW)
{
    extern __shared__ char sm[];
    const int tid = threadIdx.x;
    const uint32_t sbase = sptr(sm);
    const long rowBase = (long)blockIdx.x * 128;

    wload<128, 256>(sm + XW_SW, W1a, tid);

    // ---- fused LN + A-tile staging (4 threads per row, 32 cols each) ----
    {
        int row = tid >> 2, q = tid & 3;
        long grow = rowBase + row;
        bool valid = grow < N_NODES;
        long gr = valid ? grow : (N_NODES - 1);
        float cnt = (float)__ldg(&deg[gr]); if (cnt < 1.0f) cnt = 1.0f;
        float inv = __fdividef(1.0f, cnt);
        float4* xp = (float4*)(x + gr * 128 + q * 32);
        float4* ap = (float4*)(aggr + gr * 128 + q * 32);
        float tv[32];
        #pragma unroll
        for (int j = 0; j < 8; j++) {
            float4 xv = xp[j];
            float4 av = ap[j];
            tv[4 * j + 0] = xv.x + av.x * inv;
            tv[4 * j + 1] = xv.y + av.y * inv;
            tv[4 * j + 2] = xv.z + av.z * inv;
            tv[4 * j + 3] = xv.w + av.w * inv;
        }
        if (valid) {
            #pragma unroll
            for (int j = 0; j < 8; j++) ap[j] = make_float4(0.f, 0.f, 0.f, 0.f);
        }
        float s = 0.0f, s2 = 0.0f;
        #pragma unroll
        for (int j = 0; j < 32; j++) { s += tv[j]; s2 += tv[j] * tv[j]; }
        s  += __shfl_xor_sync(0xffffffffu, s, 1);
        s2 += __shfl_xor_sync(0xffffffffu, s2, 1);
        s  += __shfl_xor_sync(0xffffffffu, s, 2);
        s2 += __shfl_xor_sync(0xffffffffu, s2, 2);
        float mean = s * (1.0f / 128.0f);
        float var  = s2 * (1.0f / 128.0f) - mean * mean;
        float rstd = rsqrtf(var + 1e-5f);
        #pragma unroll
        for (int c8i = 0; c8i < 4; c8i++) {
            float o[8];
            #pragma unroll
            for (int j = 0; j < 8; j++) {
                int idx = c8i * 8 + j;
                int col = q * 32 + idx;
                o[j] = (tv[idx] - mean) * rstd * __ldg(&lg[col]) + __ldg(&lb[col]);
            }
            if (valid) {
                xp[c8i * 2 + 0] = make_float4(o[0], o[1], o[2], o[3]);
                xp[c8i * 2 + 1] = make_float4(o[4], o[5], o[6], o[7]);
            }
            __half2 h0 = __floats2half2_rn(o[0], o[1]);
            __half2 h1 = __floats2half2_rn(o[2], o[3]);
            __half2 h2 = __floats2half2_rn(o[4], o[5]);
            __half2 h3 = __floats2half2_rn(o[6], o[7]);
            uint4 pk = make_uint4(*(uint32_t*)&h0, *(uint32_t*)&h1,
                                  *(uint32_t*)&h2, *(uint32_t*)&h3);
            *(uint4*)(sm + XW_SE + swz(row, q * 4 + c8i, 256)) = pk;
        }
    }
    __syncthreads();
    xw_gemm_tail(sm, sbase, b1, XW, rowBase);
}

// ================= k_conv: 32-edge tiles, 256 threads, 3 CTAs/SM =================
#define CE 0
#define CM 8192
#define CI 24576
#define CONV_SMEM 24832

__global__ __launch_bounds__(256, 3) void k_conv(
    const __half* __restrict__ E, const uint2* __restrict__ W1P,
    const uint2* __restrict__ W2P, const __half* __restrict__ XW,
    const float* __restrict__ b2, const int* __restrict__ srcs,
    const int* __restrict__ dsts, float* __restrict__ aggr)
{
    extern __shared__ char sm[];
    const int tid = threadIdx.x, lane = tid & 31, wn = tid >> 5;   // 8 warps
    const int g = lane >> 2, t = lane & 3;
    const uint32_t sbase = sptr(sm);
    int* sDst = (int*)(sm + CI);
    const long ebase = (long)blockIdx.x * TEDG;

    // ---- issue ALL tile loads up front, one cp.async group ----
    // XW gather: rows are warp-uniform (row = wn + 8p), src via broadcast __ldg
    #pragma unroll
    for (int p = 0; p < 4; p++) {
        int row = wn + p * 8;
        int src = __ldg(&srcs[ebase + row]);
        CP_ASYNC16(sbase + CM + swz(row, lane, 512),
                   XW + (long)src * 256 + lane * 8);
    }
    // E tile (32x128 f16)
    #pragma unroll
    for (int p = 0; p < 2; p++) {
        int i = tid + p * 256;
        int row = i >> 4, c8 = i & 15;
        CP_ASYNC16(sbase + CE + swz(row, c8, 256), E + (ebase + row) * 128 + c8 * 8);
    }
    CP_COMMIT();
    // dst indices (needed only in epi2b; visible after S1)
    if (tid < 32) sDst[tid] = __ldg(&dsts[ebase + tid]);
    CP_WAIT0();
    __syncthreads();   // S1: E + XW + sDst all visible

    // ---- phase 1: D1 = E @ W1b ----
    float acc[2][4][4];
    #pragma unroll
    for (int mi = 0; mi < 2; mi++)
        #pragma unroll
        for (int nj = 0; nj < 4; nj++)
            #pragma unroll
            for (int q = 0; q < 4; q++) acc[mi][nj][q] = 0.0f;

    #pragma unroll
    for (int ks = 0; ks < 8; ks++) {
        uint32_t af[2][4];
        #pragma unroll
        for (int mi = 0; mi < 2; mi++)
            ldsm_x4(af[mi], sbase + CE +
                    swz(mi * 16 + (lane & 15), ks * 2 + (lane >> 4), 256));
        uint2 bf[4];
        const uint2* bp = W1P + (ks * 32 + wn * 4) * 32 + lane;
        #pragma unroll
        for (int nj = 0; nj < 4; nj++) bf[nj] = __ldg(bp + nj * 32);
        #pragma unroll
        for (int mi = 0; mi < 2; mi++)
            #pragma unroll
            for (int nj = 0; nj < 4; nj++)
                mma_16816(acc[mi][nj], af[mi], (uint32_t*)&bf[nj]);
    }

    // ---- epilogue 1: M1 = silu(D1 + XW_staged), in-place fp16 in CM ----
    // (each thread RMWs only its own fragment addresses; no barrier needed
    //  after phase 1 since CM was fully populated before S1)
    #pragma unroll
    for (int mi = 0; mi < 2; mi++) {
        int r0 = mi * 16 + g, r1 = r0 + 8;
        #pragma unroll
        for (int nj = 0; nj < 4; nj++) {
            int col = wn * 32 + nj * 8 + 2 * t;
            uint32_t a0o = CM + swz(r0, col >> 3, 512) + ((col & 7) << 1);
            uint32_t a1o = CM + swz(r1, col >> 3, 512) + ((col & 7) << 1);
            float2 f0 = __half22float2(*(__half2*)(sm + a0o));
            float2 f1 = __half22float2(*(__half2*)(sm + a1o));
            __half2 h0 = __floats2half2_rn(silu_f(acc[mi][nj][0] + f0.x),
                                           silu_f(acc[mi][nj][1] + f0.y));
            __half2 h1 = __floats2half2_rn(silu_f(acc[mi][nj][2] + f1.x),
                                           silu_f(acc[mi][nj][3] + f1.y));
            *(__half2*)(sm + a0o) = h0;
            *(__half2*)(sm + a1o) = h1;
        }
    }
    __syncthreads();   // S2: M1 complete

    // ---- phase 2: D2 = M1 @ W2 ----
    float ac2[2][2][4];
    #pragma unroll
    for (int mi = 0; mi < 2; mi++)
        #pragma unroll
        for (int nj = 0; nj < 2; nj++)
            #pragma unroll
            for (int q = 0; q < 4; q++) ac2[mi][nj][q] = 0.0f;

    #pragma unroll
    for (int ks = 0; ks < 16; ks++) {
        uint32_t af[2][4];
        #pragma unroll
        for (int mi = 0; mi < 2; mi++)
            ldsm_x4(af[mi], sbase + CM +
                    swz(mi * 16 + (lane & 15), ks * 2 + (lane >> 4), 512));
        uint2 bf[2];
        const uint2* bp = W2P + (ks * 16 + wn * 2) * 32 + lane;
        #pragma unroll
        for (int nj = 0; nj < 2; nj++) bf[nj] = __ldg(bp + nj * 32);
        #pragma unroll
        for (int mi = 0; mi < 2; mi++)
            #pragma unroll
            for (int nj = 0; nj < 2; nj++)
                mma_16816(ac2[mi][nj], af[mi], (uint32_t*)&bf[nj]);
    }

    // ---- epilogue 2a: stage silu(D2 + b2) fp16 into CE ----
    #pragma unroll
    for (int mi = 0; mi < 2; mi++) {
        int r0 = mi * 16 + g, r1 = r0 + 8;
        #pragma unroll
        for (int nj = 0; nj < 2; nj++) {
            int col = wn * 16 + nj * 8 + 2 * t;
            float2 bb = __ldg((const float2*)(b2 + col));
            __half2 h0 = __floats2half2_rn(silu_f(ac2[mi][nj][0] + bb.x),
                                           silu_f(ac2[mi][nj][1] + bb.y));
            __half2 h1 = __floats2half2_rn(silu_f(ac2[mi][nj][2] + bb.x),
                                           silu_f(ac2[mi][nj][3] + bb.y));
            *(__half2*)(sm + CE + swz(r0, col >> 3, 256) + ((col & 7) << 1)) = h0;
            *(__half2*)(sm + CE + swz(r1, col >> 3, 256) + ((col & 7) << 1)) = h1;
        }
    }
    __syncthreads();   // S3: staged D2 visible

    // ---- epilogue 2b: segmented reduction over dst-sorted rows ----
    // (warp-uniform rows: q = tid>>6 is constant within a warp)
    {
        int c = tid & 63;
        int q = tid >> 6;
        int col = 2 * c;
        float ax = 0.0f, ay = 0.0f;
        int prev = sDst[8 * q];
        #pragma unroll
        for (int r8 = 0; r8 < 8; r8++) {
            int r = 8 * q + r8;
            int d = sDst[r];
            if (d != prev) {
                red2(aggr + (long)prev * 128 + col, ax, ay);
                ax = 0.0f; ay = 0.0f; prev = d;
            }
            uint32_t hv = *(uint32_t*)(sm + CE + swz(r, col >> 3, 256) +
                                       ((col & 7) << 1));
            float2 v = __half22float2(*(__half2*)&hv);
            ax += v.x; ay += v.y;
        }
        red2(aggr + (long)prev * 128 + col, ax, ay);
    }
}

// ---------------- fused final LN + graph pooling (warp-per-node) ----------------
__global__ __launch_bounds__(128) void k_pool_ln(
    const float* __restrict__ x, const float* __restrict__ aggr,
    const int* __restrict__ deg, const float* __restrict__ lg,
    const float* __restrict__ lb, const int* __restrict__ bm,
    float* __restrict__ pool, float* __restrict__ gcnt)
{
    const int lane = threadIdx.x & 31, w = threadIdx.x >> 5;
    const long n = (long)blockIdx.x * 4 + w;
    const int c0 = lane * 4;
    float cnt = (float)__ldg(&deg[n]); if (cnt < 1.0f) cnt = 1.0f;
    float inv = __fdividef(1.0f, cnt);
    float4 xv = *(const float4*)(x + n * 128 + c0);
    float4 av = *(const float4*)(aggr + n * 128 + c0);
    float4 tv;
    tv.x = xv.x + av.x * inv; tv.y = xv.y + av.y * inv;
    tv.z = xv.z + av.z * inv; tv.w = xv.w + av.w * inv;
    float s = tv.x + tv.y + tv.z + tv.w;
    float s2 = tv.x * tv.x + tv.y * tv.y + tv.z * tv.z + tv.w * tv.w;
    #pragma unroll
    for (int o = 16; o > 0; o >>= 1) {
        s  += __shfl_xor_sync(0xffffffffu, s,  o);
        s2 += __shfl_xor_sync(0xffffffffu, s2, o);
    }
    float mean = s * (1.0f / 128.0f);
    float var  = s2 * (1.0f / 128.0f) - mean * mean;
    float rstd = rsqrtf(var + 1e-5f);
    float4 gv = *(const float4*)(lg + c0);
    float4 bv = *(const float4*)(lb + c0);
    float4 ov;
    ov.x = (tv.x - mean) * rstd * gv.x + bv.x;
    ov.y = (tv.y - mean) * rstd * gv.y + bv.y;
    ov.z = (tv.z - mean) * rstd * gv.z + bv.z;
    ov.w = (tv.w - mean) * rstd * gv.w + bv.w;
    int grp = __ldg(&bm[n]);
    float* pp = pool + (long)grp * 128 + c0;
    red2(pp,     ov.x, ov.y);
    red2(pp + 2, ov.z, ov.w);
    if (lane == 0) atomicAdd(&gcnt[grp], 1.0f);
}

// ---------------- output MLP ----------------
__global__ __launch_bounds__(128) void k_head(
    const float* __restrict__ pool, const float* __restrict__ gcnt,
    const float* __restrict__ w1, const float* __restrict__ b1,
    const float* __restrict__ w2, const float* __restrict__ b2,
    const float* __restrict__ w3, const float* __restrict__ b3,
    float* __restrict__ out)
{
    __shared__ float c[128], h1[128], h2[64];
    int g = blockIdx.x, h = threadIdx.x;
    float gc = gcnt[g]; if (gc < 1.0f) gc = 1.0f;
    c[h] = pool[g * 128 + h] / gc;
    __syncthreads();
    float a = b1[h];
    #pragma unroll 8
    for (int k = 0; k < 128; k++) a = fmaf(c[k], __ldg(&w1[k * 128 + h]), a);
    h1[h] = silu_f(a);
    __syncthreads();
    if (h < 64) {
        float a2 = b2[h];
        #pragma unroll 8
        for (int k = 0; k < 128; k++) a2 = fmaf(h1[k], __ldg(&w2[k * 64 + h]), a2);
        h2[h] = silu_f(a2);
    }
    __syncthreads();
    if (h < 3) {
        float a3 = b3[h];
        #pragma unroll
        for (int k = 0; k < 64; k++) a3 = fmaf(h2[k], __ldg(&w3[k * 3 + h]), a3);
        out[g * 3 + h] = a3;
    }
}

static inline int ceildiv(int a, int b) { return (a + b - 1) / b; }

extern "C" void kernel_launch(void* const* d_in, const int* in_sizes, int n_in,
                              void* d_out, int out_size)
{
    const float* atom_fea = (const float*)d_in[0];
    const float* nbr_fea  = (const float*)d_in[1];
    const int*   nbr_idx  = (const int*)  d_in[2];
    const int*   batch    = (const int*)  d_in[3];
    const float* emb_w    = (const float*)d_in[4];
    const float* emb_b    = (const float*)d_in[5];
    const float* emb_ln_g = (const float*)d_in[6];
    const float* emb_ln_b = (const float*)d_in[7];
    const float* edge_w   = (const float*)d_in[8];
    const float* edge_b   = (const float*)d_in[9];
    const float* conv_w1  = (const float*)d_in[10];
    const float* conv_b1  = (const float*)d_in[11];
    const float* conv_w2  = (const float*)d_in[12];
    const float* conv_b2  = (const float*)d_in[13];
    const float* ln_g     = (const float*)d_in[14];
    const float* ln_b     = (const float*)d_in[15];
    const float* out_w1   = (const float*)d_in[16];
    const float* out_b1   = (const float*)d_in[17];
    const float* out_w2   = (const float*)d_in[18];
    const float* out_b2   = (const float*)d_in[19];
    const float* out_w3   = (const float*)d_in[20];
    const float* out_b3   = (const float*)d_in[21];
    float* out = (float*)d_out;

    float *x, *aggr, *pool, *gcnt;
    __half *xh, *eh, *xw;
    uint2 *w1p, *w2p, *ewp;
    int *deg, *cur, *off, *bsum, *pos, *srcs, *dsts;
    cudaGetSymbolAddress((void**)&x,    g_x);
    cudaGetSymbolAddress((void**)&xh,   g_xh);
    cudaGetSymbolAddress((void**)&eh,   g_eh);
    cudaGetSymbolAddress((void**)&xw,   g_xw);
    cudaGetSymbolAddress((void**)&aggr, g_aggr);
    cudaGetSymbolAddress((void**)&pool, g_pool);
    cudaGetSymbolAddress((void**)&gcnt, g_gcnt);
    cudaGetSymbolAddress((void**)&w1p,  g_w1p);
    cudaGetSymbolAddress((void**)&w2p,  g_w2p);
    cudaGetSymbolAddress((void**)&ewp,  g_ewp);
    cudaGetSymbolAddress((void**)&deg,  g_deg);
    cudaGetSymbolAddress((void**)&cur,  g_cur);
    cudaGetSymbolAddress((void**)&off,  g_off);
    cudaGetSymbolAddress((void**)&bsum, g_bsum);
    cudaGetSymbolAddress((void**)&pos,  g_pos);
    cudaGetSymbolAddress((void**)&srcs, g_srcs);
    cudaGetSymbolAddress((void**)&dsts, g_dsts);

    static int attr_set = 0;
    if (!attr_set) {
        cudaFuncSetAttribute(k_xw,
                             cudaFuncAttributeMaxDynamicSharedMemorySize, XW_SMEM);
        cudaFuncSetAttribute(k_xw_ln,
                             cudaFuncAttributeMaxDynamicSharedMemorySize, XW_SMEM);
        attr_set = 1;
    }

    cudaMemsetAsync(deg,  0, N_NODES * sizeof(int), 0);
    cudaMemsetAsync(cur,  0, N_NODES * sizeof(int), 0);
    cudaMemsetAsync(aggr, 0, N_NODES * 128 * sizeof(float), 0);
    cudaMemsetAsync(pool, 0, N_GRAPHS * 128 * sizeof(float), 0);
    cudaMemsetAsync(gcnt, 0, N_GRAPHS * sizeof(float), 0);

    k_node_embed<<<N_NODES / 4, 128>>>(atom_fea, emb_w, emb_b, emb_ln_g, emb_ln_b, x, xh);
    k_deg<<<ceildiv(N_EDGES, 256), 256>>>(nbr_idx, deg, N_EDGES);
    k_cvt<<<ceildiv(NLAYERS * 8192, 256), 256>>>(conv_w1, conv_w2, edge_w,
                                                 w1p, w2p, ewp);
    k_scan1<<<SCAN_NB, 512>>>(deg, bsum);
    k_scan2<<<1, 128>>>(bsum);
    k_scan3<<<SCAN_NB, 512>>>(deg, bsum, off);
    k_scatter<<<ceildiv(N_EDGES, 256), 256>>>(nbr_idx, off, cur, pos, srcs, dsts);
    k_edge_embed<<<N_EDGES / 64, 256>>>(nbr_fea, ewp, edge_b, pos, eh);

    for (int i = 0; i < NLAYERS; i++) {
        const float* W1a = conv_w1 + (long)i * 256 * 256;
        const float* b1  = conv_b1 + (long)i * 256;
        const float* b2  = conv_b2 + (long)i * 128;

        if (i == 0)
            k_xw<<<ceildiv(N_NODES, 128), 512, XW_SMEM>>>(xh, W1a, b1, xw);
        else
            k_xw_ln<<<ceildiv(N_NODES, 128), 512, XW_SMEM>>>(
                ln_g + (i - 1) * 128, ln_b + (i - 1) * 128, deg, x, aggr,
                W1a, b1, xw);
        k_conv<<<N_UNITS, 256, CONV_SMEM>>>(eh, w1p + (long)i * 8192,
                                            w2p + (long)i * 8192, xw, b2,
                                            srcs, dsts, aggr);
    }
    k_pool_ln<<<ceildiv(N_NODES, 4), 128>>>(x, aggr, deg,
                                            ln_g + 4 * 128, ln_b + 4 * 128,
                                            batch, pool, gcnt);

    k_head<<<N_GRAPHS, 128>>>(pool, gcnt, out_w1, out_b1, out_w2, out_b2,
                              out_w3, out_b3, out);
    (void)in_sizes; (void)n_in; (void)out_size;
}

// round 16
// speedup vs baseline: 1.0173x; 1.0173x over previous
#include <cuda_runtime.h>
#include <cuda_fp16.h>
#include <cstdint>

#define N_NODES 50000
#define N_EDGES 800000
#define N_GRAPHS 1024
#define NLAYERS 5
#define TEDG 32
#define N_UNITS (N_EDGES / TEDG)   // 25000
#define SCAN_NB 98                 // ceil(50000/512)

// ---------------- scratch (device globals; no allocation allowed) ----------------
__device__ __align__(16) float  g_x[N_NODES * 128];
__device__ __align__(16) __half g_xh[N_NODES * 128];
__device__ __align__(16) __half g_eh[N_EDGES * 128];     // dst-sorted edge features
__device__ __align__(16) __half g_xw[N_NODES * 256];     // fp16 XW = x@W1a + b1
__device__ __align__(16) float  g_aggr[N_NODES * 128];
__device__ __align__(16) float  g_pool[N_GRAPHS * 128];
__device__ __align__(16) float  g_gcnt[N_GRAPHS];
__device__ __align__(16) uint2  g_w0p[NLAYERS * 8192];   // W1a fragment-packed
__device__ __align__(16) uint2  g_w1p[NLAYERS * 8192];   // W1b fragment-packed
__device__ __align__(16) uint2  g_w2p[NLAYERS * 8192];   // W2 fragment-packed
__device__ __align__(16) uint2  g_ewp[1536];             // edge_w fragment-packed
__device__ int g_deg[N_NODES];
__device__ int g_cur[N_NODES];
__device__ int g_off[N_NODES];
__device__ int g_bsum[SCAN_NB];
__device__ int g_pos[N_EDGES];
__device__ int g_srcs[N_EDGES];
__device__ int g_dsts[N_EDGES];

// silu via tanh.approx: sigma(x) = 0.5 + 0.5*tanh(x/2); 1 MUFU + FMA-pipe ops
__device__ __forceinline__ float silu_f(float v) {
    float t;
    asm("tanh.approx.f32 %0, %1;" : "=f"(t) : "f"(0.5f * v));
    return v * fmaf(t, 0.5f, 0.5f);
}

__device__ __forceinline__ uint32_t sptr(const void* p) {
    return (uint32_t)__cvta_generic_to_shared(p);
}
__device__ __forceinline__ uint32_t swz(int row, int c8, int rowBytes) {
    return (uint32_t)(row * rowBytes + (((c8 ^ (row & 7)) << 4)));
}
__device__ __forceinline__ void ldsm_x4(uint32_t* r, uint32_t addr) {
    asm volatile("ldmatrix.sync.aligned.m8n8.x4.shared.b16 {%0,%1,%2,%3}, [%4];\n"
                 : "=r"(r[0]), "=r"(r[1]), "=r"(r[2]), "=r"(r[3]) : "r"(addr));
}
__device__ __forceinline__ void mma_16816(float* c, const uint32_t* a, const uint32_t* b) {
    asm volatile(
        "mma.sync.aligned.m16n8k16.row.col.f32.f16.f16.f32 "
        "{%0,%1,%2,%3}, {%4,%5,%6,%7}, {%8,%9}, {%0,%1,%2,%3};\n"
        : "+f"(c[0]), "+f"(c[1]), "+f"(c[2]), "+f"(c[3])
        : "r"(a[0]), "r"(a[1]), "r"(a[2]), "r"(a[3]), "r"(b[0]), "r"(b[1]));
}
__device__ __forceinline__ void red2(float* p, float a, float b) {
    asm volatile("red.global.add.v2.f32 [%0], {%1,%2};" :: "l"(p), "f"(a), "f"(b) : "memory");
}
#define CP_ASYNC16(sdst, gsrc) \
    asm volatile("cp.async.cg.shared.global [%0], [%1], 16;" :: "r"(sdst), "l"(gsrc) : "memory")
#define CP_COMMIT() asm volatile("cp.async.commit_group;" ::: "memory")
#define CP_WAIT0()  asm volatile("cp.async.wait_group 0;" ::: "memory")
#define CP_WAIT1()  asm volatile("cp.async.wait_group 1;" ::: "memory")

// ---------------- node embedding (warp-per-node) ----------------
__global__ __launch_bounds__(128) void k_node_embed(
    const float* __restrict__ atom, const float* __restrict__ w,
    const float* __restrict__ b, const float* __restrict__ lg,
    const float* __restrict__ lb, float* __restrict__ x, __half* __restrict__ xh)
{
    const int lane = threadIdx.x & 31, wp = threadIdx.x >> 5;
    const long n = (long)blockIdx.x * 4 + wp;
    const int c0 = lane * 4;
    float4 a = *(const float4*)(atom + n * 4);
    float v[4];
    #pragma unroll
    for (int c = 0; c < 4; c++) {
        int col = c0 + c;
        float acc = __ldg(&b[col]);
        acc = fmaf(a.x, __ldg(&w[0 * 128 + col]), acc);
        acc = fmaf(a.y, __ldg(&w[1 * 128 + col]), acc);
        acc = fmaf(a.z, __ldg(&w[2 * 128 + col]), acc);
        acc = fmaf(a.w, __ldg(&w[3 * 128 + col]), acc);
        v[c] = acc;
    }
    float s = v[0] + v[1] + v[2] + v[3];
    float s2 = v[0] * v[0] + v[1] * v[1] + v[2] * v[2] + v[3] * v[3];
    #pragma unroll
    for (int o = 16; o > 0; o >>= 1) {
        s  += __shfl_xor_sync(0xffffffffu, s,  o);
        s2 += __shfl_xor_sync(0xffffffffu, s2, o);
    }
    float mean = s * (1.0f / 128.0f);
    float var  = s2 * (1.0f / 128.0f) - mean * mean;
    float rstd = rsqrtf(var + 1e-5f);
    float4 gv = *(const float4*)(lg + c0);
    float4 bv = *(const float4*)(lb + c0);
    float o0 = silu_f((v[0] - mean) * rstd * gv.x + bv.x);
    float o1 = silu_f((v[1] - mean) * rstd * gv.y + bv.y);
    float o2 = silu_f((v[2] - mean) * rstd * gv.z + bv.z);
    float o3 = silu_f((v[3] - mean) * rstd * gv.w + bv.w);
    *(float4*)(x + n * 128 + c0) = make_float4(o0, o1, o2, o3);
    __half2 h0 = __floats2half2_rn(o0, o1);
    __half2 h1 = __floats2half2_rn(o2, o3);
    *(uint2*)(xh + n * 128 + c0) = make_uint2(*(uint32_t*)&h0, *(uint32_t*)&h1);
}

// ---------------- degree count ----------------
__global__ void k_deg(const int* __restrict__ idx, int* __restrict__ deg, int nE) {
    int i = blockIdx.x * blockDim.x + threadIdx.x;
    if (i < nE) atomicAdd(&deg[idx[2 * i + 1]], 1);
}

// ---------------- parallel exclusive scan (3 kernels) ----------------
__global__ __launch_bounds__(512) void k_scan1(const int* __restrict__ deg,
                                               int* __restrict__ bsum)
{
    __shared__ int ws[16];
    int tid = threadIdx.x, lane = tid & 31, w = tid >> 5;
    int i = blockIdx.x * 512 + tid;
    int v = (i < N_NODES) ? deg[i] : 0;
    int s = v;
    #pragma unroll
    for (int o = 16; o > 0; o >>= 1) s += __shfl_xor_sync(0xffffffffu, s, o);
    if (lane == 0) ws[w] = s;
    __syncthreads();
    if (tid == 0) {
        int tot = 0;
        #pragma unroll
        for (int j = 0; j < 16; j++) tot += ws[j];
        bsum[blockIdx.x] = tot;
    }
}

__global__ __launch_bounds__(128) void k_scan2(int* __restrict__ bsum)
{
    __shared__ int ws[4];
    int tid = threadIdx.x, lane = tid & 31, w = tid >> 5;
    int v = (tid < SCAN_NB) ? bsum[tid] : 0;
    int incl = v;
    #pragma unroll
    for (int o = 1; o < 32; o <<= 1) {
        int t2 = __shfl_up_sync(0xffffffffu, incl, o);
        if (lane >= o) incl += t2;
    }
    if (lane == 31) ws[w] = incl;
    __syncthreads();
    int add = 0;
    for (int j = 0; j < w; j++) add += ws[j];
    incl += add;
    if (tid < SCAN_NB) bsum[tid] = incl - v;   // exclusive
}

__global__ __launch_bounds__(512) void k_scan3(const int* __restrict__ deg,
                                               const int* __restrict__ bsum,
                                               int* __restrict__ off)
{
    __shared__ int ws[16];
    int tid = threadIdx.x, lane = tid & 31, w = tid >> 5;
    int i = blockIdx.x * 512 + tid;
    int v = (i < N_NODES) ? deg[i] : 0;
    int incl = v;
    #pragma unroll
    for (int o = 1; o < 32; o <<= 1) {
        int t2 = __shfl_up_sync(0xffffffffu, incl, o);
        if (lane >= o) incl += t2;
    }
    if (lane == 31) ws[w] = incl;
    __syncthreads();
    int add = 0;
    for (int j = 0; j < w; j++) add += ws[j];
    if (i < N_NODES) off[i] = incl - v + add + bsum[blockIdx.x];
}

// ---------------- edge scatter (counting sort by dst) ----------------
__global__ void k_scatter(const int* __restrict__ nbr, const int* __restrict__ off,
                          int* __restrict__ cur, int* __restrict__ pos,
                          int* __restrict__ srcs, int* __restrict__ dsts)
{
    int i = blockIdx.x * blockDim.x + threadIdx.x;
    if (i < N_EDGES) {
        int d = nbr[2 * i + 1];
        int p = off[d] + atomicAdd(&cur[d], 1);
        pos[i] = p;
        srcs[p] = nbr[2 * i];
        dsts[p] = d;
    }
}

// ---------------- weight fragment packing ----------------
__global__ __launch_bounds__(256) void k_cvt(
    const float* __restrict__ w1, const float* __restrict__ w2,
    const float* __restrict__ ew,
    uint2* __restrict__ w0p, uint2* __restrict__ w1p,
    uint2* __restrict__ w2p, uint2* __restrict__ ewp)
{
    int i = blockIdx.x * 256 + threadIdx.x;
    if (i >= NLAYERS * 8192) return;
    int lane = i & 31;
    int t = lane & 3, g = lane >> 2;
    {   // W0P: B[k][n] = conv_w1[k*256 + n] (rows 0..127); 8 ks x 32 nt
        int r = i >> 5;
        int nt = r & 31; r >>= 5;
        int ks = r & 7;  int layer = r >> 3;
        const float* W = w1 + (long)layer * 65536;
        int n = nt * 8 + g, k0 = ks * 16 + 2 * t;
        __half2 a = __floats2half2_rn(W[(k0    ) * 256 + n], W[(k0 + 1) * 256 + n]);
        __half2 b = __floats2half2_rn(W[(k0 + 8) * 256 + n], W[(k0 + 9) * 256 + n]);
        w0p[i] = make_uint2(*(uint32_t*)&a, *(uint32_t*)&b);
    }
    {   // W1P: B[k][n] = conv_w1[(128+k)*256 + n]; 8 ks x 32 nt
        int r = i >> 5;
        int nt = r & 31; r >>= 5;
        int ks = r & 7;  int layer = r >> 3;
        const float* W = w1 + (long)layer * 65536;
        int n = nt * 8 + g, k0 = ks * 16 + 2 * t;
        __half2 a = __floats2half2_rn(W[(128 + k0) * 256 + n], W[(129 + k0) * 256 + n]);
        __half2 b = __floats2half2_rn(W[(136 + k0) * 256 + n], W[(137 + k0) * 256 + n]);
        w1p[i] = make_uint2(*(uint32_t*)&a, *(uint32_t*)&b);
    }
    {   // W2P: B[k][n] = conv_w2[k*128 + n]; 16 ks x 16 nt
        int r = i >> 5;
        int nt = r & 15; r >>= 4;
        int ks = r & 15; int layer = r >> 4;
        const float* W = w2 + (long)layer * 32768;
        int n = nt * 8 + g, k0 = ks * 16 + 2 * t;
        __half2 a = __floats2half2_rn(W[k0 * 128 + n],       W[(k0 + 1) * 128 + n]);
        __half2 b = __floats2half2_rn(W[(k0 + 8) * 128 + n], W[(k0 + 9) * 128 + n]);
        w2p[i] = make_uint2(*(uint32_t*)&a, *(uint32_t*)&b);
    }
    if (i < 1536) {   // EWP
        int r = i >> 5;
        int nt = r & 15;
        int ks = r >> 4;
        int n = nt * 8 + g, k0 = ks * 16 + 2 * t;
        float v0 = (k0     < 41) ? ew[(k0    ) * 128 + n] : 0.0f;
        float v1 = (k0 + 1 < 41) ? ew[(k0 + 1) * 128 + n] : 0.0f;
        float v2 = (k0 + 8 < 41) ? ew[(k0 + 8) * 128 + n] : 0.0f;
        float v3 = (k0 + 9 < 41) ? ew[(k0 + 9) * 128 + n] : 0.0f;
        __half2 a = __floats2half2_rn(v0, v1);
        __half2 b = __floats2half2_rn(v2, v3);
        ewp[i] = make_uint2(*(uint32_t*)&a, *(uint32_t*)&b);
    }
}

// ---------------- edge embedding (HMMA) ----------------
__global__ __launch_bounds__(256) void k_edge_embed(
    const float* __restrict__ nbr, const uint2* __restrict__ EWP,
    const float* __restrict__ b, const int* __restrict__ pos, __half* __restrict__ e)
{
    __shared__ __align__(16) char sA[64 * 128];
    __shared__ int spos[64];
    const int tid = threadIdx.x, lane = tid & 31, warp = tid >> 5;
    const int wm = (warp & 3) * 16, wnh = warp >> 2;
    const int g = lane >> 2, t = lane & 3;
    const uint32_t sbase = sptr(sA);
    const long e0 = (long)blockIdx.x * 64;

    if (tid < 64) spos[tid] = __ldg(&pos[e0 + tid]);
    #pragma unroll
    for (int p = 0; p < 16; p++) {
        int i = tid + p * 256;
        int row = i >> 6, c = i & 63;
        float v = (c < 41) ? __ldg(&nbr[(e0 + row) * 41 + c]) : 0.0f;
        __half hv = __float2half_rn(v);
        *(__half*)(sA + swz(row, c >> 3, 128) + ((c & 7) << 1)) = hv;
    }
    __syncthreads();

    float acc[8][4];
    #pragma unroll
    for (int nj = 0; nj < 8; nj++)
        #pragma unroll
        for (int q = 0; q < 4; q++) acc[nj][q] = 0.0f;

    #pragma unroll
    for (int ks = 0; ks < 3; ks++) {
        uint32_t af[4];
        ldsm_x4(af, sbase + swz(wm + (lane & 15), ks * 2 + (lane >> 4), 128));
        uint2 bf[8];
        const uint2* bp = EWP + (ks * 16 + wnh * 8) * 32 + lane;
        #pragma unroll
        for (int nj = 0; nj < 8; nj++) bf[nj] = __ldg(bp + nj * 32);
        #pragma unroll
        for (int nj = 0; nj < 8; nj++)
            mma_16816(acc[nj], af, (uint32_t*)&bf[nj]);
    }

    int r0 = wm + g, r1 = r0 + 8;
    long p0 = spos[r0], p1 = spos[r1];
    #pragma unroll
    for (int nj = 0; nj < 8; nj++) {
        int col = wnh * 64 + nj * 8 + 2 * t;
        float2 bb = __ldg((const float2*)(b + col));
        __half2 h0 = __floats2half2_rn(silu_f(acc[nj][0] + bb.x),
                                       silu_f(acc[nj][1] + bb.y));
        __half2 h1 = __floats2half2_rn(silu_f(acc[nj][2] + bb.x),
                                       silu_f(acc[nj][3] + bb.y));
        *(uint32_t*)(e + p0 * 128 + col) = *(uint32_t*)&h0;
        *(uint32_t*)(e + p1 * 128 + col) = *(uint32_t*)&h1;
    }
}

// ================= k_xw family (packed-B GEMM; smem = A tile only) =================
#define XW_SMEM 32768

// GEMM tail: A tile in smem (swizzled, rowBytes 256), B from packed gmem fragments
__device__ __forceinline__ void xw_gemm_tail(
    uint32_t sbase, const uint2* __restrict__ W0P,
    const float* __restrict__ b1, __half* __restrict__ XW, long rowBase)
{
    const int tid = threadIdx.x, lane = tid & 31, warp = tid >> 5;
    const int wm = (warp & 3) * 32, wn = warp >> 2;
    const int g = lane >> 2, t = lane & 3;

    float acc[2][8][4];
    #pragma unroll
    for (int mi = 0; mi < 2; mi++)
        #pragma unroll
        for (int nj = 0; nj < 8; nj++)
            #pragma unroll
            for (int q = 0; q < 4; q++) acc[mi][nj][q] = 0.0f;

    #pragma unroll
    for (int ks = 0; ks < 8; ks++) {
        uint32_t af[2][4];
        #pragma unroll
        for (int mi = 0; mi < 2; mi++)
            ldsm_x4(af[mi], sbase +
                    swz(wm + mi * 16 + (lane & 15), ks * 2 + (lane >> 4), 256));
        uint2 bf[8];
        const uint2* bp = W0P + (ks * 32 + wn * 8) * 32 + lane;
        #pragma unroll
        for (int nj = 0; nj < 8; nj++) bf[nj] = __ldg(bp + nj * 32);
        #pragma unroll
        for (int mi = 0; mi < 2; mi++)
            #pragma unroll
            for (int nj = 0; nj < 8; nj++)
                mma_16816(acc[mi][nj], af[mi], (uint32_t*)&bf[nj]);
    }

    #pragma unroll
    for (int mi = 0; mi < 2; mi++) {
        long g0 = rowBase + wm + mi * 16 + g, g1 = g0 + 8;
        #pragma unroll
        for (int nj = 0; nj < 8; nj++) {
            int col = wn * 64 + nj * 8 + 2 * t;
            float2 bb = *(const float2*)(b1 + col);
            if (g0 < N_NODES) {
                __half2 h = __floats2half2_rn(acc[mi][nj][0] + bb.x, acc[mi][nj][1] + bb.y);
                *(uint32_t*)(XW + g0 * 256 + col) = *(uint32_t*)&h;
            }
            if (g1 < N_NODES) {
                __half2 h = __floats2half2_rn(acc[mi][nj][2] + bb.x, acc[mi][nj][3] + bb.y);
                *(uint32_t*)(XW + g1 * 256 + col) = *(uint32_t*)&h;
            }
        }
    }
}

// layer-0 k_xw: A tile from precomputed xh
__global__ __launch_bounds__(512) void k_xw(
    const __half* __restrict__ Xh, const uint2* __restrict__ W0P,
    const float* __restrict__ b1, __half* __restrict__ XW)
{
    extern __shared__ char sm[];
    const int tid = threadIdx.x;
    const uint32_t sbase = sptr(sm);
    const long rowBase = (long)blockIdx.x * 128;

    {
        int row = tid >> 2, cb = (tid & 3) * 4;
        long grow = rowBase + row;
        if (grow >= N_NODES) grow = N_NODES - 1;
        const uint4* p = (const uint4*)(Xh + grow * 128) + cb;
        #pragma unroll
        for (int j = 0; j < 4; j++)
            *(uint4*)(sm + swz(row, cb + j, 256)) = __ldg(p + j);
    }
    __syncthreads();
    xw_gemm_tail(sbase, W0P, b1, XW, rowBase);
}

// layers 1..4: fused LN(x + aggr/deg) -> x, zero aggr, stage A, GEMM
__global__ __launch_bounds__(512) void k_xw_ln(
    const float* __restrict__ lg, const float* __restrict__ lb,
    const int* __restrict__ deg, float* __restrict__ x, float* __restrict__ aggr,
    const uint2* __restrict__ W0P, const float* __restrict__ b1,
    __half* __restrict__ XW)
{
    extern __shared__ char sm[];
    const int tid = threadIdx.x;
    const uint32_t sbase = sptr(sm);
    const long rowBase = (long)blockIdx.x * 128;

    // ---- fused LN + A-tile staging (4 threads per row, 32 cols each) ----
    {
        int row = tid >> 2, q = tid & 3;
        long grow = rowBase + row;
        bool valid = grow < N_NODES;
        long gr = valid ? grow : (N_NODES - 1);
        float cnt = (float)__ldg(&deg[gr]); if (cnt < 1.0f) cnt = 1.0f;
        float inv = __fdividef(1.0f, cnt);
        float4* xp = (float4*)(x + gr * 128 + q * 32);
        float4* ap = (float4*)(aggr + gr * 128 + q * 32);
        float tv[32];
        #pragma unroll
        for (int j = 0; j < 8; j++) {
            float4 xv = xp[j];
            float4 av = ap[j];
            tv[4 * j + 0] = xv.x + av.x * inv;
            tv[4 * j + 1] = xv.y + av.y * inv;
            tv[4 * j + 2] = xv.z + av.z * inv;
            tv[4 * j + 3] = xv.w + av.w * inv;
        }
        if (valid) {
            #pragma unroll
            for (int j = 0; j < 8; j++) ap[j] = make_float4(0.f, 0.f, 0.f, 0.f);
        }
        float s = 0.0f, s2 = 0.0f;
        #pragma unroll
        for (int j = 0; j < 32; j++) { s += tv[j]; s2 += tv[j] * tv[j]; }
        s  += __shfl_xor_sync(0xffffffffu, s, 1);
        s2 += __shfl_xor_sync(0xffffffffu, s2, 1);
        s  += __shfl_xor_sync(0xffffffffu, s, 2);
        s2 += __shfl_xor_sync(0xffffffffu, s2, 2);
        float mean = s * (1.0f / 128.0f);
        float var  = s2 * (1.0f / 128.0f) - mean * mean;
        float rstd = rsqrtf(var + 1e-5f);
        #pragma unroll
        for (int c8i = 0; c8i < 4; c8i++) {
            float o[8];
            #pragma unroll
            for (int j = 0; j < 8; j++) {
                int idx = c8i * 8 + j;
                int col = q * 32 + idx;
                o[j] = (tv[idx] - mean) * rstd * __ldg(&lg[col]) + __ldg(&lb[col]);
            }
            if (valid) {
                xp[c8i * 2 + 0] = make_float4(o[0], o[1], o[2], o[3]);
                xp[c8i * 2 + 1] = make_float4(o[4], o[5], o[6], o[7]);
            }
            __half2 h0 = __floats2half2_rn(o[0], o[1]);
            __half2 h1 = __floats2half2_rn(o[2], o[3]);
            __half2 h2 = __floats2half2_rn(o[4], o[5]);
            __half2 h3 = __floats2half2_rn(o[6], o[7]);
            uint4 pk = make_uint4(*(uint32_t*)&h0, *(uint32_t*)&h1,
                                  *(uint32_t*)&h2, *(uint32_t*)&h3);
            *(uint4*)(sm + swz(row, q * 4 + c8i, 256)) = pk;
        }
    }
    __syncthreads();
    xw_gemm_tail(sbase, W0P, b1, XW, rowBase);
}

// ================= k_conv: 32-edge tiles, 256 threads, 3 CTAs/SM (R13 exact) =================
#define CE 0
#define CM 8192
#define CI 24576
#define CONV_SMEM 24832

__global__ __launch_bounds__(256, 3) void k_conv(
    const __half* __restrict__ E, const uint2* __restrict__ W1P,
    const uint2* __restrict__ W2P, const __half* __restrict__ XW,
    const float* __restrict__ b2, const int* __restrict__ srcs,
    const int* __restrict__ dsts, float* __restrict__ aggr)
{
    extern __shared__ char sm[];
    const int tid = threadIdx.x, lane = tid & 31, wn = tid >> 5;   // 8 warps
    const int g = lane >> 2, t = lane & 3;
    const uint32_t sbase = sptr(sm);
    int* sSrc = (int*)(sm + CI);
    int* sDst = sSrc + 32;
    const long ebase = (long)blockIdx.x * TEDG;

    // group A: indices
    if (tid < 8) CP_ASYNC16(sbase + CI + tid * 16, srcs + ebase + tid * 4);
    else if (tid < 16) CP_ASYNC16(sbase + CI + 128 + (tid - 8) * 16, dsts + ebase + (tid - 8) * 4);
    CP_COMMIT();
    // group B: E tile (32x128 f16)
    #pragma unroll
    for (int p = 0; p < 2; p++) {
        int i = tid + p * 256;
        int row = i >> 4, c8 = i & 15;
        CP_ASYNC16(sbase + CE + swz(row, c8, 256), E + (ebase + row) * 128 + c8 * 8);
    }
    CP_COMMIT();
    CP_WAIT1();        // idx done
    __syncthreads();   // S1: sSrc visible

    // group C: XW gather
    #pragma unroll
    for (int p = 0; p < 4; p++) {
        int i = tid + p * 256;
        int row = i >> 5, c8 = i & 31;
        CP_ASYNC16(sbase + CM + swz(row, c8, 512),
                   XW + (long)sSrc[row] * 256 + c8 * 8);
    }
    CP_COMMIT();
    CP_WAIT1();        // E done
    __syncthreads();   // S2: E visible

    // ---- phase 1: D1 = E @ W1b ----
    float acc[2][4][4];
    #pragma unroll
    for (int mi = 0; mi < 2; mi++)
        #pragma unroll
        for (int nj = 0; nj < 4; nj++)
            #pragma unroll
            for (int q = 0; q < 4; q++) acc[mi][nj][q] = 0.0f;

    #pragma unroll
    for (int ks = 0; ks < 8; ks++) {
        uint32_t af[2][4];
        #pragma unroll
        for (int mi = 0; mi < 2; mi++)
            ldsm_x4(af[mi], sbase + CE +
                    swz(mi * 16 + (lane & 15), ks * 2 + (lane >> 4), 256));
        uint2 bf[4];
        const uint2* bp = W1P + (ks * 32 + wn * 4) * 32 + lane;
        #pragma unroll
        for (int nj = 0; nj < 4; nj++) bf[nj] = __ldg(bp + nj * 32);
        #pragma unroll
        for (int mi = 0; mi < 2; mi++)
            #pragma unroll
            for (int nj = 0; nj < 4; nj++)
                mma_16816(acc[mi][nj], af[mi], (uint32_t*)&bf[nj]);
    }
    CP_WAIT0();
    __syncthreads();   // S3

    // ---- epilogue 1: M1 = silu(D1 + XW_staged), in-place fp16 in CM ----
    #pragma unroll
    for (int mi = 0; mi < 2; mi++) {
        int r0 = mi * 16 + g, r1 = r0 + 8;
        #pragma unroll
        for (int nj = 0; nj < 4; nj++) {
            int col = wn * 32 + nj * 8 + 2 * t;
            uint32_t a0o = CM + swz(r0, col >> 3, 512) + ((col & 7) << 1);
            uint32_t a1o = CM + swz(r1, col >> 3, 512) + ((col & 7) << 1);
            float2 f0 = __half22float2(*(__half2*)(sm + a0o));
            float2 f1 = __half22float2(*(__half2*)(sm + a1o));
            __half2 h0 = __floats2half2_rn(silu_f(acc[mi][nj][0] + f0.x),
                                           silu_f(acc[mi][nj][1] + f0.y));
            __half2 h1 = __floats2half2_rn(silu_f(acc[mi][nj][2] + f1.x),
                                           silu_f(acc[mi][nj][3] + f1.y));
            *(__half2*)(sm + a0o) = h0;
            *(__half2*)(sm + a1o) = h1;
        }
    }
    __syncthreads();   // S4

    // ---- phase 2: D2 = M1 @ W2 ----
    float ac2[2][2][4];
    #pragma unroll
    for (int mi = 0; mi < 2; mi++)
        #pragma unroll
        for (int nj = 0; nj < 2; nj++)
            #pragma unroll
            for (int q = 0; q < 4; q++) ac2[mi][nj][q] = 0.0f;

    #pragma unroll
    for (int ks = 0; ks < 16; ks++) {
        uint32_t af[2][4];
        #pragma unroll
        for (int mi = 0; mi < 2; mi++)
            ldsm_x4(af[mi], sbase + CM +
                    swz(mi * 16 + (lane & 15), ks * 2 + (lane >> 4), 512));
        uint2 bf[2];
        const uint2* bp = W2P + (ks * 16 + wn * 2) * 32 + lane;
        #pragma unroll
        for (int nj = 0; nj < 2; nj++) bf[nj] = __ldg(bp + nj * 32);
        #pragma unroll
        for (int mi = 0; mi < 2; mi++)
            #pragma unroll
            for (int nj = 0; nj < 2; nj++)
                mma_16816(ac2[mi][nj], af[mi], (uint32_t*)&bf[nj]);
    }

    // ---- epilogue 2a: stage silu(D2 + b2) fp16 into CE ----
    #pragma unroll
    for (int mi = 0; mi < 2; mi++) {
        int r0 = mi * 16 + g, r1 = r0 + 8;
        #pragma unroll
        for (int nj = 0; nj < 2; nj++) {
            int col = wn * 16 + nj * 8 + 2 * t;
            float2 bb = __ldg((const float2*)(b2 + col));
            __half2 h0 = __floats2half2_rn(silu_f(ac2[mi][nj][0] + bb.x),
                                           silu_f(ac2[mi][nj][1] + bb.y));
            __half2 h1 = __floats2half2_rn(silu_f(ac2[mi][nj][2] + bb.x),
                                           silu_f(ac2[mi][nj][3] + bb.y));
            *(__half2*)(sm + CE + swz(r0, col >> 3, 256) + ((col & 7) << 1)) = h0;
            *(__half2*)(sm + CE + swz(r1, col >> 3, 256) + ((col & 7) << 1)) = h1;
        }
    }
    __syncthreads();   // S5

    // ---- epilogue 2b: segmented reduction over dst-sorted rows ----
    // (warp-uniform rows: q = tid>>6 is constant within a warp)
    {
        int c = tid & 63;
        int q = tid >> 6;
        int col = 2 * c;
        float ax = 0.0f, ay = 0.0f;
        int prev = sDst[8 * q];
        #pragma unroll
        for (int r8 = 0; r8 < 8; r8++) {
            int r = 8 * q + r8;
            int d = sDst[r];
            if (d != prev) {
                red2(aggr + (long)prev * 128 + col, ax, ay);
                ax = 0.0f; ay = 0.0f; prev = d;
            }
            uint32_t hv = *(uint32_t*)(sm + CE + swz(r, col >> 3, 256) +
                                       ((col & 7) << 1));
            float2 v = __half22float2(*(__half2*)&hv);
            ax += v.x; ay += v.y;
        }
        red2(aggr + (long)prev * 128 + col, ax, ay);
    }
}

// ---------------- fused final LN + graph pooling (warp-per-node) ----------------
__global__ __launch_bounds__(128) void k_pool_ln(
    const float* __restrict__ x, const float* __restrict__ aggr,
    const int* __restrict__ deg, const float* __restrict__ lg,
    const float* __restrict__ lb, const int* __restrict__ bm,
    float* __restrict__ pool, float* __restrict__ gcnt)
{
    const int lane = threadIdx.x & 31, w = threadIdx.x >> 5;
    const long n = (long)blockIdx.x * 4 + w;
    const int c0 = lane * 4;
    float cnt = (float)__ldg(&deg[n]); if (cnt < 1.0f) cnt = 1.0f;
    float inv = __fdividef(1.0f, cnt);
    float4 xv = *(const float4*)(x + n * 128 + c0);
    float4 av = *(const float4*)(aggr + n * 128 + c0);
    float4 tv;
    tv.x = xv.x + av.x * inv; tv.y = xv.y + av.y * inv;
    tv.z = xv.z + av.z * inv; tv.w = xv.w + av.w * inv;
    float s = tv.x + tv.y + tv.z + tv.w;
    float s2 = tv.x * tv.x + tv.y * tv.y + tv.z * tv.z + tv.w * tv.w;
    #pragma unroll
    for (int o = 16; o > 0; o >>= 1) {
        s  += __shfl_xor_sync(0xffffffffu, s,  o);
        s2 += __shfl_xor_sync(0xffffffffu, s2, o);
    }
    float mean = s * (1.0f / 128.0f);
    float var  = s2 * (1.0f / 128.0f) - mean * mean;
    float rstd = rsqrtf(var + 1e-5f);
    float4 gv = *(const float4*)(lg + c0);
    float4 bv = *(const float4*)(lb + c0);
    float4 ov;
    ov.x = (tv.x - mean) * rstd * gv.x + bv.x;
    ov.y = (tv.y - mean) * rstd * gv.y + bv.y;
    ov.z = (tv.z - mean) * rstd * gv.z + bv.z;
    ov.w = (tv.w - mean) * rstd * gv.w + bv.w;
    int grp = __ldg(&bm[n]);
    float* pp = pool + (long)grp * 128 + c0;
    red2(pp,     ov.x, ov.y);
    red2(pp + 2, ov.z, ov.w);
    if (lane == 0) atomicAdd(&gcnt[grp], 1.0f);
}

// ---------------- output MLP ----------------
__global__ __launch_bounds__(128) void k_head(
    const float* __restrict__ pool, const float* __restrict__ gcnt,
    const float* __restrict__ w1, const float* __restrict__ b1,
    const float* __restrict__ w2, const float* __restrict__ b2,
    const float* __restrict__ w3, const float* __restrict__ b3,
    float* __restrict__ out)
{
    __shared__ float c[128], h1[128], h2[64];
    int g = blockIdx.x, h = threadIdx.x;
    float gc = gcnt[g]; if (gc < 1.0f) gc = 1.0f;
    c[h] = pool[g * 128 + h] / gc;
    __syncthreads();
    float a = b1[h];
    #pragma unroll 8
    for (int k = 0; k < 128; k++) a = fmaf(c[k], __ldg(&w1[k * 128 + h]), a);
    h1[h] = silu_f(a);
    __syncthreads();
    if (h < 64) {
        float a2 = b2[h];
        #pragma unroll 8
        for (int k = 0; k < 128; k++) a2 = fmaf(h1[k], __ldg(&w2[k * 64 + h]), a2);
        h2[h] = silu_f(a2);
    }
    __syncthreads();
    if (h < 3) {
        float a3 = b3[h];
        #pragma unroll
        for (int k = 0; k < 64; k++) a3 = fmaf(h2[k], __ldg(&w3[k * 3 + h]), a3);
        out[g * 3 + h] = a3;
    }
}

static inline int ceildiv(int a, int b) { return (a + b - 1) / b; }

extern "C" void kernel_launch(void* const* d_in, const int* in_sizes, int n_in,
                              void* d_out, int out_size)
{
    const float* atom_fea = (const float*)d_in[0];
    const float* nbr_fea  = (const float*)d_in[1];
    const int*   nbr_idx  = (const int*)  d_in[2];
    const int*   batch    = (const int*)  d_in[3];
    const float* emb_w    = (const float*)d_in[4];
    const float* emb_b    = (const float*)d_in[5];
    const float* emb_ln_g = (const float*)d_in[6];
    const float* emb_ln_b = (const float*)d_in[7];
    const float* edge_w   = (const float*)d_in[8];
    const float* edge_b   = (const float*)d_in[9];
    const float* conv_w1  = (const float*)d_in[10];
    const float* conv_b1  = (const float*)d_in[11];
    const float* conv_w2  = (const float*)d_in[12];
    const float* conv_b2  = (const float*)d_in[13];
    const float* ln_g     = (const float*)d_in[14];
    const float* ln_b     = (const float*)d_in[15];
    const float* out_w1   = (const float*)d_in[16];
    const float* out_b1   = (const float*)d_in[17];
    const float* out_w2   = (const float*)d_in[18];
    const float* out_b2   = (const float*)d_in[19];
    const float* out_w3   = (const float*)d_in[20];
    const float* out_b3   = (const float*)d_in[21];
    float* out = (float*)d_out;

    float *x, *aggr, *pool, *gcnt;
    __half *xh, *eh, *xw;
    uint2 *w0p, *w1p, *w2p, *ewp;
    int *deg, *cur, *off, *bsum, *pos, *srcs, *dsts;
    cudaGetSymbolAddress((void**)&x,    g_x);
    cudaGetSymbolAddress((void**)&xh,   g_xh);
    cudaGetSymbolAddress((void**)&eh,   g_eh);
    cudaGetSymbolAddress((void**)&xw,   g_xw);
    cudaGetSymbolAddress((void**)&aggr, g_aggr);
    cudaGetSymbolAddress((void**)&pool, g_pool);
    cudaGetSymbolAddress((void**)&gcnt, g_gcnt);
    cudaGetSymbolAddress((void**)&w0p,  g_w0p);
    cudaGetSymbolAddress((void**)&w1p,  g_w1p);
    cudaGetSymbolAddress((void**)&w2p,  g_w2p);
    cudaGetSymbolAddress((void**)&ewp,  g_ewp);
    cudaGetSymbolAddress((void**)&deg,  g_deg);
    cudaGetSymbolAddress((void**)&cur,  g_cur);
    cudaGetSymbolAddress((void**)&off,  g_off);
    cudaGetSymbolAddress((void**)&bsum, g_bsum);
    cudaGetSymbolAddress((void**)&pos,  g_pos);
    cudaGetSymbolAddress((void**)&srcs, g_srcs);
    cudaGetSymbolAddress((void**)&dsts, g_dsts);

    static int attr_set = 0;
    if (!attr_set) {
        cudaFuncSetAttribute(k_xw,
                             cudaFuncAttributeMaxDynamicSharedMemorySize, XW_SMEM);
        cudaFuncSetAttribute(k_xw_ln,
                             cudaFuncAttributeMaxDynamicSharedMemorySize, XW_SMEM);
        attr_set = 1;
    }

    cudaMemsetAsync(deg,  0, N_NODES * sizeof(int), 0);
    cudaMemsetAsync(cur,  0, N_NODES * sizeof(int), 0);
    cudaMemsetAsync(aggr, 0, N_NODES * 128 * sizeof(float), 0);
    cudaMemsetAsync(pool, 0, N_GRAPHS * 128 * sizeof(float), 0);
    cudaMemsetAsync(gcnt, 0, N_GRAPHS * sizeof(float), 0);

    k_node_embed<<<N_NODES / 4, 128>>>(atom_fea, emb_w, emb_b, emb_ln_g, emb_ln_b, x, xh);
    k_deg<<<ceildiv(N_EDGES, 256), 256>>>(nbr_idx, deg, N_EDGES);
    k_cvt<<<ceildiv(NLAYERS * 8192, 256), 256>>>(conv_w1, conv_w2, edge_w,
                                                 w0p, w1p, w2p, ewp);
    k_scan1<<<SCAN_NB, 512>>>(deg, bsum);
    k_scan2<<<1, 128>>>(bsum);
    k_scan3<<<SCAN_NB, 512>>>(deg, bsum, off);
    k_scatter<<<ceildiv(N_EDGES, 256), 256>>>(nbr_idx, off, cur, pos, srcs, dsts);
    k_edge_embed<<<N_EDGES / 64, 256>>>(nbr_fea, ewp, edge_b, pos, eh);

    for (int i = 0; i < NLAYERS; i++) {
        const float* b1 = conv_b1 + (long)i * 256;
        const float* b2 = conv_b2 + (long)i * 128;

        if (i == 0)
            k_xw<<<ceildiv(N_NODES, 128), 512, XW_SMEM>>>(
                xh, w0p + (long)i * 8192, b1, xw);
        else
            k_xw_ln<<<ceildiv(N_NODES, 128), 512, XW_SMEM>>>(
                ln_g + (i - 1) * 128, ln_b + (i - 1) * 128, deg, x, aggr,
                w0p + (long)i * 8192, b1, xw);
        k_conv<<<N_UNITS, 256, CONV_SMEM>>>(eh, w1p + (long)i * 8192,
                                            w2p + (long)i * 8192, xw, b2,
                                            srcs, dsts, aggr);
    }
    k_pool_ln<<<ceildiv(N_NODES, 4), 128>>>(x, aggr, deg,
                                            ln_g + 4 * 128, ln_b + 4 * 128,
                                            batch, pool, gcnt);

    k_head<<<N_GRAPHS, 128>>>(pool, gcnt, out_w1, out_b1, out_w2, out_b2,
                              out_w3, out_b3, out);
    (void)in_sizes; (void)n_in; (void)out_size;
}

// round 17
// speedup vs baseline: 1.0229x; 1.0055x over previous
#include <cuda_runtime.h>
#include <cuda_fp16.h>
#include <cstdint>

#define N_NODES 50000
#define N_EDGES 800000
#define N_GRAPHS 1024
#define NLAYERS 5
#define TEDG 32
#define N_UNITS (N_EDGES / TEDG)   // 25000
#define SCAN_NB 98                 // ceil(50000/512)

// ---------------- scratch (device globals; no allocation allowed) ----------------
__device__ __align__(16) float  g_x[N_NODES * 128];
__device__ __align__(16) __half g_xh[N_NODES * 128];
__device__ __align__(16) __half g_eh[N_EDGES * 128];     // dst-sorted edge features
__device__ __align__(16) __half g_xw[N_NODES * 256];     // fp16 XW = x@W1a + b1
__device__ __align__(16) float  g_aggr[N_NODES * 128];
__device__ __align__(16) float  g_pool[N_GRAPHS * 128];
__device__ __align__(16) float  g_gcnt[N_GRAPHS];
__device__ __align__(16) uint2  g_w0p[NLAYERS * 8192];   // W1a fragment-packed
__device__ __align__(16) uint2  g_w1p[NLAYERS * 8192];   // W1b fragment-packed
__device__ __align__(16) uint2  g_w2p[NLAYERS * 8192];   // W2 fragment-packed
__device__ __align__(16) uint2  g_ewp[1536];             // edge_w fragment-packed
__device__ int g_deg[N_NODES];
__device__ int g_cur[N_NODES];
__device__ int g_off[N_NODES];
__device__ int g_bsum[SCAN_NB];
__device__ int g_pos[N_EDGES];
__device__ int g_srcs[N_EDGES];
__device__ int g_dsts[N_EDGES];

// silu via tanh.approx: sigma(x) = 0.5 + 0.5*tanh(x/2); 1 MUFU + FMA-pipe ops
__device__ __forceinline__ float silu_f(float v) {
    float t;
    asm("tanh.approx.f32 %0, %1;" : "=f"(t) : "f"(0.5f * v));
    return v * fmaf(t, 0.5f, 0.5f);
}

__device__ __forceinline__ uint32_t sptr(const void* p) {
    return (uint32_t)__cvta_generic_to_shared(p);
}
__device__ __forceinline__ uint32_t swz(int row, int c8, int rowBytes) {
    return (uint32_t)(row * rowBytes + (((c8 ^ (row & 7)) << 4)));
}
__device__ __forceinline__ void ldsm_x4(uint32_t* r, uint32_t addr) {
    asm volatile("ldmatrix.sync.aligned.m8n8.x4.shared.b16 {%0,%1,%2,%3}, [%4];\n"
                 : "=r"(r[0]), "=r"(r[1]), "=r"(r[2]), "=r"(r[3]) : "r"(addr));
}
__device__ __forceinline__ void mma_16816(float* c, const uint32_t* a, const uint32_t* b) {
    asm volatile(
        "mma.sync.aligned.m16n8k16.row.col.f32.f16.f16.f32 "
        "{%0,%1,%2,%3}, {%4,%5,%6,%7}, {%8,%9}, {%0,%1,%2,%3};\n"
        : "+f"(c[0]), "+f"(c[1]), "+f"(c[2]), "+f"(c[3])
        : "r"(a[0]), "r"(a[1]), "r"(a[2]), "r"(a[3]), "r"(b[0]), "r"(b[1]));
}
__device__ __forceinline__ void red2(float* p, float a, float b) {
    asm volatile("red.global.add.v2.f32 [%0], {%1,%2};" :: "l"(p), "f"(a), "f"(b) : "memory");
}
#define CP_ASYNC16(sdst, gsrc) \
    asm volatile("cp.async.cg.shared.global [%0], [%1], 16;" :: "r"(sdst), "l"(gsrc) : "memory")
#define CP_COMMIT() asm volatile("cp.async.commit_group;" ::: "memory")
#define CP_WAIT0()  asm volatile("cp.async.wait_group 0;" ::: "memory")
#define CP_WAIT1()  asm volatile("cp.async.wait_group 1;" ::: "memory")

// ---------------- node embedding (warp-per-node) ----------------
__global__ __launch_bounds__(128) void k_node_embed(
    const float* __restrict__ atom, const float* __restrict__ w,
    const float* __restrict__ b, const float* __restrict__ lg,
    const float* __restrict__ lb, float* __restrict__ x, __half* __restrict__ xh)
{
    const int lane = threadIdx.x & 31, wp = threadIdx.x >> 5;
    const long n = (long)blockIdx.x * 4 + wp;
    const int c0 = lane * 4;
    float4 a = *(const float4*)(atom + n * 4);
    float v[4];
    #pragma unroll
    for (int c = 0; c < 4; c++) {
        int col = c0 + c;
        float acc = __ldg(&b[col]);
        acc = fmaf(a.x, __ldg(&w[0 * 128 + col]), acc);
        acc = fmaf(a.y, __ldg(&w[1 * 128 + col]), acc);
        acc = fmaf(a.z, __ldg(&w[2 * 128 + col]), acc);
        acc = fmaf(a.w, __ldg(&w[3 * 128 + col]), acc);
        v[c] = acc;
    }
    float s = v[0] + v[1] + v[2] + v[3];
    float s2 = v[0] * v[0] + v[1] * v[1] + v[2] * v[2] + v[3] * v[3];
    #pragma unroll
    for (int o = 16; o > 0; o >>= 1) {
        s  += __shfl_xor_sync(0xffffffffu, s,  o);
        s2 += __shfl_xor_sync(0xffffffffu, s2, o);
    }
    float mean = s * (1.0f / 128.0f);
    float var  = s2 * (1.0f / 128.0f) - mean * mean;
    float rstd = rsqrtf(var + 1e-5f);
    float4 gv = *(const float4*)(lg + c0);
    float4 bv = *(const float4*)(lb + c0);
    float o0 = silu_f((v[0] - mean) * rstd * gv.x + bv.x);
    float o1 = silu_f((v[1] - mean) * rstd * gv.y + bv.y);
    float o2 = silu_f((v[2] - mean) * rstd * gv.z + bv.z);
    float o3 = silu_f((v[3] - mean) * rstd * gv.w + bv.w);
    *(float4*)(x + n * 128 + c0) = make_float4(o0, o1, o2, o3);
    __half2 h0 = __floats2half2_rn(o0, o1);
    __half2 h1 = __floats2half2_rn(o2, o3);
    *(uint2*)(xh + n * 128 + c0) = make_uint2(*(uint32_t*)&h0, *(uint32_t*)&h1);
}

// ---------------- degree count ----------------
__global__ void k_deg(const int* __restrict__ idx, int* __restrict__ deg, int nE) {
    int i = blockIdx.x * blockDim.x + threadIdx.x;
    if (i < nE) atomicAdd(&deg[idx[2 * i + 1]], 1);
}

// ---------------- parallel exclusive scan (3 kernels) ----------------
__global__ __launch_bounds__(512) void k_scan1(const int* __restrict__ deg,
                                               int* __restrict__ bsum)
{
    __shared__ int ws[16];
    int tid = threadIdx.x, lane = tid & 31, w = tid >> 5;
    int i = blockIdx.x * 512 + tid;
    int v = (i < N_NODES) ? deg[i] : 0;
    int s = v;
    #pragma unroll
    for (int o = 16; o > 0; o >>= 1) s += __shfl_xor_sync(0xffffffffu, s, o);
    if (lane == 0) ws[w] = s;
    __syncthreads();
    if (tid == 0) {
        int tot = 0;
        #pragma unroll
        for (int j = 0; j < 16; j++) tot += ws[j];
        bsum[blockIdx.x] = tot;
    }
}

__global__ __launch_bounds__(128) void k_scan2(int* __restrict__ bsum)
{
    __shared__ int ws[4];
    int tid = threadIdx.x, lane = tid & 31, w = tid >> 5;
    int v = (tid < SCAN_NB) ? bsum[tid] : 0;
    int incl = v;
    #pragma unroll
    for (int o = 1; o < 32; o <<= 1) {
        int t2 = __shfl_up_sync(0xffffffffu, incl, o);
        if (lane >= o) incl += t2;
    }
    if (lane == 31) ws[w] = incl;
    __syncthreads();
    int add = 0;
    for (int j = 0; j < w; j++) add += ws[j];
    incl += add;
    if (tid < SCAN_NB) bsum[tid] = incl - v;   // exclusive
}

__global__ __launch_bounds__(512) void k_scan3(const int* __restrict__ deg,
                                               const int* __restrict__ bsum,
                                               int* __restrict__ off)
{
    __shared__ int ws[16];
    int tid = threadIdx.x, lane = tid & 31, w = tid >> 5;
    int i = blockIdx.x * 512 + tid;
    int v = (i < N_NODES) ? deg[i] : 0;
    int incl = v;
    #pragma unroll
    for (int o = 1; o < 32; o <<= 1) {
        int t2 = __shfl_up_sync(0xffffffffu, incl, o);
        if (lane >= o) incl += t2;
    }
    if (lane == 31) ws[w] = incl;
    __syncthreads();
    int add = 0;
    for (int j = 0; j < w; j++) add += ws[j];
    if (i < N_NODES) off[i] = incl - v + add + bsum[blockIdx.x];
}

// ---------------- edge scatter (counting sort by dst) ----------------
__global__ void k_scatter(const int* __restrict__ nbr, const int* __restrict__ off,
                          int* __restrict__ cur, int* __restrict__ pos,
                          int* __restrict__ srcs, int* __restrict__ dsts)
{
    int i = blockIdx.x * blockDim.x + threadIdx.x;
    if (i < N_EDGES) {
        int d = nbr[2 * i + 1];
        int p = off[d] + atomicAdd(&cur[d], 1);
        pos[i] = p;
        srcs[p] = nbr[2 * i];
        dsts[p] = d;
    }
}

// ---------------- weight fragment packing ----------------
__global__ __launch_bounds__(256) void k_cvt(
    const float* __restrict__ w1, const float* __restrict__ w2,
    const float* __restrict__ ew,
    uint2* __restrict__ w0p, uint2* __restrict__ w1p,
    uint2* __restrict__ w2p, uint2* __restrict__ ewp)
{
    int i = blockIdx.x * 256 + threadIdx.x;
    if (i >= NLAYERS * 8192) return;
    int lane = i & 31;
    int t = lane & 3, g = lane >> 2;
    {   // W0P: B[k][n] = conv_w1[k*256 + n] (rows 0..127); 8 ks x 32 nt
        int r = i >> 5;
        int nt = r & 31; r >>= 5;
        int ks = r & 7;  int layer = r >> 3;
        const float* W = w1 + (long)layer * 65536;
        int n = nt * 8 + g, k0 = ks * 16 + 2 * t;
        __half2 a = __floats2half2_rn(W[(k0    ) * 256 + n], W[(k0 + 1) * 256 + n]);
        __half2 b = __floats2half2_rn(W[(k0 + 8) * 256 + n], W[(k0 + 9) * 256 + n]);
        w0p[i] = make_uint2(*(uint32_t*)&a, *(uint32_t*)&b);
    }
    {   // W1P: B[k][n] = conv_w1[(128+k)*256 + n]; 8 ks x 32 nt
        int r = i >> 5;
        int nt = r & 31; r >>= 5;
        int ks = r & 7;  int layer = r >> 3;
        const float* W = w1 + (long)layer * 65536;
        int n = nt * 8 + g, k0 = ks * 16 + 2 * t;
        __half2 a = __floats2half2_rn(W[(128 + k0) * 256 + n], W[(129 + k0) * 256 + n]);
        __half2 b = __floats2half2_rn(W[(136 + k0) * 256 + n], W[(137 + k0) * 256 + n]);
        w1p[i] = make_uint2(*(uint32_t*)&a, *(uint32_t*)&b);
    }
    {   // W2P: B[k][n] = conv_w2[k*128 + n]; 16 ks x 16 nt
        int r = i >> 5;
        int nt = r & 15; r >>= 4;
        int ks = r & 15; int layer = r >> 4;
        const float* W = w2 + (long)layer * 32768;
        int n = nt * 8 + g, k0 = ks * 16 + 2 * t;
        __half2 a = __floats2half2_rn(W[k0 * 128 + n],       W[(k0 + 1) * 128 + n]);
        __half2 b = __floats2half2_rn(W[(k0 + 8) * 128 + n], W[(k0 + 9) * 128 + n]);
        w2p[i] = make_uint2(*(uint32_t*)&a, *(uint32_t*)&b);
    }
    if (i < 1536) {   // EWP
        int r = i >> 5;
        int nt = r & 15;
        int ks = r >> 4;
        int n = nt * 8 + g, k0 = ks * 16 + 2 * t;
        float v0 = (k0     < 41) ? ew[(k0    ) * 128 + n] : 0.0f;
        float v1 = (k0 + 1 < 41) ? ew[(k0 + 1) * 128 + n] : 0.0f;
        float v2 = (k0 + 8 < 41) ? ew[(k0 + 8) * 128 + n] : 0.0f;
        float v3 = (k0 + 9 < 41) ? ew[(k0 + 9) * 128 + n] : 0.0f;
        __half2 a = __floats2half2_rn(v0, v1);
        __half2 b = __floats2half2_rn(v2, v3);
        ewp[i] = make_uint2(*(uint32_t*)&a, *(uint32_t*)&b);
    }
}

// ---------------- edge embedding (HMMA) ----------------
__global__ __launch_bounds__(256) void k_edge_embed(
    const float* __restrict__ nbr, const uint2* __restrict__ EWP,
    const float* __restrict__ b, const int* __restrict__ pos, __half* __restrict__ e)
{
    __shared__ __align__(16) char sA[64 * 128];
    __shared__ int spos[64];
    const int tid = threadIdx.x, lane = tid & 31, warp = tid >> 5;
    const int wm = (warp & 3) * 16, wnh = warp >> 2;
    const int g = lane >> 2, t = lane & 3;
    const uint32_t sbase = sptr(sA);
    const long e0 = (long)blockIdx.x * 64;

    if (tid < 64) spos[tid] = __ldg(&pos[e0 + tid]);
    #pragma unroll
    for (int p = 0; p < 16; p++) {
        int i = tid + p * 256;
        int row = i >> 6, c = i & 63;
        float v = (c < 41) ? __ldg(&nbr[(e0 + row) * 41 + c]) : 0.0f;
        __half hv = __float2half_rn(v);
        *(__half*)(sA + swz(row, c >> 3, 128) + ((c & 7) << 1)) = hv;
    }
    __syncthreads();

    float acc[8][4];
    #pragma unroll
    for (int nj = 0; nj < 8; nj++)
        #pragma unroll
        for (int q = 0; q < 4; q++) acc[nj][q] = 0.0f;

    #pragma unroll
    for (int ks = 0; ks < 3; ks++) {
        uint32_t af[4];
        ldsm_x4(af, sbase + swz(wm + (lane & 15), ks * 2 + (lane >> 4), 128));
        uint2 bf[8];
        const uint2* bp = EWP + (ks * 16 + wnh * 8) * 32 + lane;
        #pragma unroll
        for (int nj = 0; nj < 8; nj++) bf[nj] = __ldg(bp + nj * 32);
        #pragma unroll
        for (int nj = 0; nj < 8; nj++)
            mma_16816(acc[nj], af, (uint32_t*)&bf[nj]);
    }

    int r0 = wm + g, r1 = r0 + 8;
    long p0 = spos[r0], p1 = spos[r1];
    #pragma unroll
    for (int nj = 0; nj < 8; nj++) {
        int col = wnh * 64 + nj * 8 + 2 * t;
        float2 bb = __ldg((const float2*)(b + col));
        __half2 h0 = __floats2half2_rn(silu_f(acc[nj][0] + bb.x),
                                       silu_f(acc[nj][1] + bb.y));
        __half2 h1 = __floats2half2_rn(silu_f(acc[nj][2] + bb.x),
                                       silu_f(acc[nj][3] + bb.y));
        *(uint32_t*)(e + p0 * 128 + col) = *(uint32_t*)&h0;
        *(uint32_t*)(e + p1 * 128 + col) = *(uint32_t*)&h1;
    }
}

// ================= k_xw family (packed-B GEMM; smem = A tile only) =================
#define XW_SMEM 32768

__device__ __forceinline__ void xw_gemm_tail(
    uint32_t sbase, const uint2* __restrict__ W0P,
    const float* __restrict__ b1, __half* __restrict__ XW, long rowBase)
{
    const int tid = threadIdx.x, lane = tid & 31, warp = tid >> 5;
    const int wm = (warp & 3) * 32, wn = warp >> 2;
    const int g = lane >> 2, t = lane & 3;

    float acc[2][8][4];
    #pragma unroll
    for (int mi = 0; mi < 2; mi++)
        #pragma unroll
        for (int nj = 0; nj < 8; nj++)
            #pragma unroll
            for (int q = 0; q < 4; q++) acc[mi][nj][q] = 0.0f;

    #pragma unroll
    for (int ks = 0; ks < 8; ks++) {
        uint32_t af[2][4];
        #pragma unroll
        for (int mi = 0; mi < 2; mi++)
            ldsm_x4(af[mi], sbase +
                    swz(wm + mi * 16 + (lane & 15), ks * 2 + (lane >> 4), 256));
        uint2 bf[8];
        const uint2* bp = W0P + (ks * 32 + wn * 8) * 32 + lane;
        #pragma unroll
        for (int nj = 0; nj < 8; nj++) bf[nj] = __ldg(bp + nj * 32);
        #pragma unroll
        for (int mi = 0; mi < 2; mi++)
            #pragma unroll
            for (int nj = 0; nj < 8; nj++)
                mma_16816(acc[mi][nj], af[mi], (uint32_t*)&bf[nj]);
    }

    #pragma unroll
    for (int mi = 0; mi < 2; mi++) {
        long g0 = rowBase + wm + mi * 16 + g, g1 = g0 + 8;
        #pragma unroll
        for (int nj = 0; nj < 8; nj++) {
            int col = wn * 64 + nj * 8 + 2 * t;
            float2 bb = *(const float2*)(b1 + col);
            if (g0 < N_NODES) {
                __half2 h = __floats2half2_rn(acc[mi][nj][0] + bb.x, acc[mi][nj][1] + bb.y);
                *(uint32_t*)(XW + g0 * 256 + col) = *(uint32_t*)&h;
            }
            if (g1 < N_NODES) {
                __half2 h = __floats2half2_rn(acc[mi][nj][2] + bb.x, acc[mi][nj][3] + bb.y);
                *(uint32_t*)(XW + g1 * 256 + col) = *(uint32_t*)&h;
            }
        }
    }
}

__global__ __launch_bounds__(512) void k_xw(
    const __half* __restrict__ Xh, const uint2* __restrict__ W0P,
    const float* __restrict__ b1, __half* __restrict__ XW)
{
    extern __shared__ char sm[];
    const int tid = threadIdx.x;
    const uint32_t sbase = sptr(sm);
    const long rowBase = (long)blockIdx.x * 128;

    {
        int row = tid >> 2, cb = (tid & 3) * 4;
        long grow = rowBase + row;
        if (grow >= N_NODES) grow = N_NODES - 1;
        const uint4* p = (const uint4*)(Xh + grow * 128) + cb;
        #pragma unroll
        for (int j = 0; j < 4; j++)
            *(uint4*)(sm + swz(row, cb + j, 256)) = __ldg(p + j);
    }
    __syncthreads();
    xw_gemm_tail(sbase, W0P, b1, XW, rowBase);
}

__global__ __launch_bounds__(512) void k_xw_ln(
    const float* __restrict__ lg, const float* __restrict__ lb,
    const int* __restrict__ deg, float* __restrict__ x, float* __restrict__ aggr,
    const uint2* __restrict__ W0P, const float* __restrict__ b1,
    __half* __restrict__ XW)
{
    extern __shared__ char sm[];
    const int tid = threadIdx.x;
    const uint32_t sbase = sptr(sm);
    const long rowBase = (long)blockIdx.x * 128;

    {
        int row = tid >> 2, q = tid & 3;
        long grow = rowBase + row;
        bool valid = grow < N_NODES;
        long gr = valid ? grow : (N_NODES - 1);
        float cnt = (float)__ldg(&deg[gr]); if (cnt < 1.0f) cnt = 1.0f;
        float inv = __fdividef(1.0f, cnt);
        float4* xp = (float4*)(x + gr * 128 + q * 32);
        float4* ap = (float4*)(aggr + gr * 128 + q * 32);
        float tv[32];
        #pragma unroll
        for (int j = 0; j < 8; j++) {
            float4 xv = xp[j];
            float4 av = ap[j];
            tv[4 * j + 0] = xv.x + av.x * inv;
            tv[4 * j + 1] = xv.y + av.y * inv;
            tv[4 * j + 2] = xv.z + av.z * inv;
            tv[4 * j + 3] = xv.w + av.w * inv;
        }
        if (valid) {
            #pragma unroll
            for (int j = 0; j < 8; j++) ap[j] = make_float4(0.f, 0.f, 0.f, 0.f);
        }
        float s = 0.0f, s2 = 0.0f;
        #pragma unroll
        for (int j = 0; j < 32; j++) { s += tv[j]; s2 += tv[j] * tv[j]; }
        s  += __shfl_xor_sync(0xffffffffu, s, 1);
        s2 += __shfl_xor_sync(0xffffffffu, s2, 1);
        s  += __shfl_xor_sync(0xffffffffu, s, 2);
        s2 += __shfl_xor_sync(0xffffffffu, s2, 2);
        float mean = s * (1.0f / 128.0f);
        float var  = s2 * (1.0f / 128.0f) - mean * mean;
        float rstd = rsqrtf(var + 1e-5f);
        #pragma unroll
        for (int c8i = 0; c8i < 4; c8i++) {
            float o[8];
            #pragma unroll
            for (int j = 0; j < 8; j++) {
                int idx = c8i * 8 + j;
                int col = q * 32 + idx;
                o[j] = (tv[idx] - mean) * rstd * __ldg(&lg[col]) + __ldg(&lb[col]);
            }
            if (valid) {
                xp[c8i * 2 + 0] = make_float4(o[0], o[1], o[2], o[3]);
                xp[c8i * 2 + 1] = make_float4(o[4], o[5], o[6], o[7]);
            }
            __half2 h0 = __floats2half2_rn(o[0], o[1]);
            __half2 h1 = __floats2half2_rn(o[2], o[3]);
            __half2 h2 = __floats2half2_rn(o[4], o[5]);
            __half2 h3 = __floats2half2_rn(o[6], o[7]);
            uint4 pk = make_uint4(*(uint32_t*)&h0, *(uint32_t*)&h1,
                                  *(uint32_t*)&h2, *(uint32_t*)&h3);
            *(uint4*)(sm + swz(row, q * 4 + c8i, 256)) = pk;
        }
    }
    __syncthreads();
    xw_gemm_tail(sbase, W0P, b1, XW, rowBase);
}

// ================= k_conv: 32-edge tiles, 256 threads, 3 CTAs/SM (R13 exact) =================
#define CE 0
#define CM 8192
#define CI 24576
#define CONV_SMEM 24832

__global__ __launch_bounds__(256, 3) void k_conv(
    const __half* __restrict__ E, const uint2* __restrict__ W1P,
    const uint2* __restrict__ W2P, const __half* __restrict__ XW,
    const float* __restrict__ b2, const int* __restrict__ srcs,
    const int* __restrict__ dsts, float* __restrict__ aggr)
{
    extern __shared__ char sm[];
    const int tid = threadIdx.x, lane = tid & 31, wn = tid >> 5;   // 8 warps
    const int g = lane >> 2, t = lane & 3;
    const uint32_t sbase = sptr(sm);
    int* sSrc = (int*)(sm + CI);
    int* sDst = sSrc + 32;
    const long ebase = (long)blockIdx.x * TEDG;

    // group A: indices
    if (tid < 8) CP_ASYNC16(sbase + CI + tid * 16, srcs + ebase + tid * 4);
    else if (tid < 16) CP_ASYNC16(sbase + CI + 128 + (tid - 8) * 16, dsts + ebase + (tid - 8) * 4);
    CP_COMMIT();
    // group B: E tile (32x128 f16)
    #pragma unroll
    for (int p = 0; p < 2; p++) {
        int i = tid + p * 256;
        int row = i >> 4, c8 = i & 15;
        CP_ASYNC16(sbase + CE + swz(row, c8, 256), E + (ebase + row) * 128 + c8 * 8);
    }
    CP_COMMIT();
    CP_WAIT1();        // idx done
    __syncthreads();   // S1: sSrc visible

    // group C: XW gather
    #pragma unroll
    for (int p = 0; p < 4; p++) {
        int i = tid + p * 256;
        int row = i >> 5, c8 = i & 31;
        CP_ASYNC16(sbase + CM + swz(row, c8, 512),
                   XW + (long)sSrc[row] * 256 + c8 * 8);
    }
    CP_COMMIT();
    CP_WAIT1();        // E done
    __syncthreads();   // S2: E visible

    // ---- phase 1: D1 = E @ W1b ----
    float acc[2][4][4];
    #pragma unroll
    for (int mi = 0; mi < 2; mi++)
        #pragma unroll
        for (int nj = 0; nj < 4; nj++)
            #pragma unroll
            for (int q = 0; q < 4; q++) acc[mi][nj][q] = 0.0f;

    #pragma unroll
    for (int ks = 0; ks < 8; ks++) {
        uint32_t af[2][4];
        #pragma unroll
        for (int mi = 0; mi < 2; mi++)
            ldsm_x4(af[mi], sbase + CE +
                    swz(mi * 16 + (lane & 15), ks * 2 + (lane >> 4), 256));
        uint2 bf[4];
        const uint2* bp = W1P + (ks * 32 + wn * 4) * 32 + lane;
        #pragma unroll
        for (int nj = 0; nj < 4; nj++) bf[nj] = __ldg(bp + nj * 32);
        #pragma unroll
        for (int mi = 0; mi < 2; mi++)
            #pragma unroll
            for (int nj = 0; nj < 4; nj++)
                mma_16816(acc[mi][nj], af[mi], (uint32_t*)&bf[nj]);
    }
    CP_WAIT0();
    __syncthreads();   // S3

    // ---- epilogue 1: M1 = silu(D1 + XW_staged), in-place fp16 in CM ----
    #pragma unroll
    for (int mi = 0; mi < 2; mi++) {
        int r0 = mi * 16 + g, r1 = r0 + 8;
        #pragma unroll
        for (int nj = 0; nj < 4; nj++) {
            int col = wn * 32 + nj * 8 + 2 * t;
            uint32_t a0o = CM + swz(r0, col >> 3, 512) + ((col & 7) << 1);
            uint32_t a1o = CM + swz(r1, col >> 3, 512) + ((col & 7) << 1);
            float2 f0 = __half22float2(*(__half2*)(sm + a0o));
            float2 f1 = __half22float2(*(__half2*)(sm + a1o));
            __half2 h0 = __floats2half2_rn(silu_f(acc[mi][nj][0] + f0.x),
                                           silu_f(acc[mi][nj][1] + f0.y));
            __half2 h1 = __floats2half2_rn(silu_f(acc[mi][nj][2] + f1.x),
                                           silu_f(acc[mi][nj][3] + f1.y));
            *(__half2*)(sm + a0o) = h0;
            *(__half2*)(sm + a1o) = h1;
        }
    }
    __syncthreads();   // S4

    // ---- phase 2: D2 = M1 @ W2 ----
    float ac2[2][2][4];
    #pragma unroll
    for (int mi = 0; mi < 2; mi++)
        #pragma unroll
        for (int nj = 0; nj < 2; nj++)
            #pragma unroll
            for (int q = 0; q < 4; q++) ac2[mi][nj][q] = 0.0f;

    #pragma unroll
    for (int ks = 0; ks < 16; ks++) {
        uint32_t af[2][4];
        #pragma unroll
        for (int mi = 0; mi < 2; mi++)
            ldsm_x4(af[mi], sbase + CM +
                    swz(mi * 16 + (lane & 15), ks * 2 + (lane >> 4), 512));
        uint2 bf[2];
        const uint2* bp = W2P + (ks * 16 + wn * 2) * 32 + lane;
        #pragma unroll
        for (int nj = 0; nj < 2; nj++) bf[nj] = __ldg(bp + nj * 32);
        #pragma unroll
        for (int mi = 0; mi < 2; mi++)
            #pragma unroll
            for (int nj = 0; nj < 2; nj++)
                mma_16816(ac2[mi][nj], af[mi], (uint32_t*)&bf[nj]);
    }

    // ---- epilogue 2a: stage silu(D2 + b2) fp16 into CE ----
    #pragma unroll
    for (int mi = 0; mi < 2; mi++) {
        int r0 = mi * 16 + g, r1 = r0 + 8;
        #pragma unroll
        for (int nj = 0; nj < 2; nj++) {
            int col = wn * 16 + nj * 8 + 2 * t;
            float2 bb = __ldg((const float2*)(b2 + col));
            __half2 h0 = __floats2half2_rn(silu_f(ac2[mi][nj][0] + bb.x),
                                           silu_f(ac2[mi][nj][1] + bb.y));
            __half2 h1 = __floats2half2_rn(silu_f(ac2[mi][nj][2] + bb.x),
                                           silu_f(ac2[mi][nj][3] + bb.y));
            *(__half2*)(sm + CE + swz(r0, col >> 3, 256) + ((col & 7) << 1)) = h0;
            *(__half2*)(sm + CE + swz(r1, col >> 3, 256) + ((col & 7) << 1)) = h1;
        }
    }
    __syncthreads();   // S5

    // ---- epilogue 2b: segmented reduction over dst-sorted rows ----
    // (warp-uniform rows: q = tid>>6 is constant within a warp)
    {
        int c = tid & 63;
        int q = tid >> 6;
        int col = 2 * c;
        float ax = 0.0f, ay = 0.0f;
        int prev = sDst[8 * q];
        #pragma unroll
        for (int r8 = 0; r8 < 8; r8++) {
            int r = 8 * q + r8;
            int d = sDst[r];
            if (d != prev) {
                red2(aggr + (long)prev * 128 + col, ax, ay);
                ax = 0.0f; ay = 0.0f; prev = d;
            }
            uint32_t hv = *(uint32_t*)(sm + CE + swz(r, col >> 3, 256) +
                                       ((col & 7) << 1));
            float2 v = __half22float2(*(__half2*)&hv);
            ax += v.x; ay += v.y;
        }
        red2(aggr + (long)prev * 128 + col, ax, ay);
    }
}

// ---------------- fused final LN + graph pooling (warp-per-node) ----------------
__global__ __launch_bounds__(128) void k_pool_ln(
    const float* __restrict__ x, const float* __restrict__ aggr,
    const int* __restrict__ deg, const float* __restrict__ lg,
    const float* __restrict__ lb, const int* __restrict__ bm,
    float* __restrict__ pool, float* __restrict__ gcnt)
{
    const int lane = threadIdx.x & 31, w = threadIdx.x >> 5;
    const long n = (long)blockIdx.x * 4 + w;
    const int c0 = lane * 4;
    float cnt = (float)__ldg(&deg[n]); if (cnt < 1.0f) cnt = 1.0f;
    float inv = __fdividef(1.0f, cnt);
    float4 xv = *(const float4*)(x + n * 128 + c0);
    float4 av = *(const float4*)(aggr + n * 128 + c0);
    float4 tv;
    tv.x = xv.x + av.x * inv; tv.y = xv.y + av.y * inv;
    tv.z = xv.z + av.z * inv; tv.w = xv.w + av.w * inv;
    float s = tv.x + tv.y + tv.z + tv.w;
    float s2 = tv.x * tv.x + tv.y * tv.y + tv.z * tv.z + tv.w * tv.w;
    #pragma unroll
    for (int o = 16; o > 0; o >>= 1) {
        s  += __shfl_xor_sync(0xffffffffu, s,  o);
        s2 += __shfl_xor_sync(0xffffffffu, s2, o);
    }
    float mean = s * (1.0f / 128.0f);
    float var  = s2 * (1.0f / 128.0f) - mean * mean;
    float rstd = rsqrtf(var + 1e-5f);
    float4 gv = *(const float4*)(lg + c0);
    float4 bv = *(const float4*)(lb + c0);
    float4 ov;
    ov.x = (tv.x - mean) * rstd * gv.x + bv.x;
    ov.y = (tv.y - mean) * rstd * gv.y + bv.y;
    ov.z = (tv.z - mean) * rstd * gv.z + bv.z;
    ov.w = (tv.w - mean) * rstd * gv.w + bv.w;
    int grp = __ldg(&bm[n]);
    float* pp = pool + (long)grp * 128 + c0;
    red2(pp,     ov.x, ov.y);
    red2(pp + 2, ov.z, ov.w);
    if (lane == 0) atomicAdd(&gcnt[grp], 1.0f);
}

// ---------------- output MLP ----------------
__global__ __launch_bounds__(128) void k_head(
    const float* __restrict__ pool, const float* __restrict__ gcnt,
    const float* __restrict__ w1, const float* __restrict__ b1,
    const float* __restrict__ w2, const float* __restrict__ b2,
    const float* __restrict__ w3, const float* __restrict__ b3,
    float* __restrict__ out)
{
    __shared__ float c[128], h1[128], h2[64];
    int g = blockIdx.x, h = threadIdx.x;
    float gc = gcnt[g]; if (gc < 1.0f) gc = 1.0f;
    c[h] = pool[g * 128 + h] / gc;
    __syncthreads();
    float a = b1[h];
    #pragma unroll 8
    for (int k = 0; k < 128; k++) a = fmaf(c[k], __ldg(&w1[k * 128 + h]), a);
    h1[h] = silu_f(a);
    __syncthreads();
    if (h < 64) {
        float a2 = b2[h];
        #pragma unroll 8
        for (int k = 0; k < 128; k++) a2 = fmaf(h1[k], __ldg(&w2[k * 64 + h]), a2);
        h2[h] = silu_f(a2);
    }
    __syncthreads();
    if (h < 3) {
        float a3 = b3[h];
        #pragma unroll
        for (int k = 0; k < 64; k++) a3 = fmaf(h2[k], __ldg(&w3[k * 3 + h]), a3);
        out[g * 3 + h] = a3;
    }
}

static inline int ceildiv(int a, int b) { return (a + b - 1) / b; }

extern "C" void kernel_launch(void* const* d_in, const int* in_sizes, int n_in,
                              void* d_out, int out_size)
{
    const float* atom_fea = (const float*)d_in[0];
    const float* nbr_fea  = (const float*)d_in[1];
    const int*   nbr_idx  = (const int*)  d_in[2];
    const int*   batch    = (const int*)  d_in[3];
    const float* emb_w    = (const float*)d_in[4];
    const float* emb_b    = (const float*)d_in[5];
    const float* emb_ln_g = (const float*)d_in[6];
    const float* emb_ln_b = (const float*)d_in[7];
    const float* edge_w   = (const float*)d_in[8];
    const float* edge_b   = (const float*)d_in[9];
    const float* conv_w1  = (const float*)d_in[10];
    const float* conv_b1  = (const float*)d_in[11];
    const float* conv_w2  = (const float*)d_in[12];
    const float* conv_b2  = (const float*)d_in[13];
    const float* ln_g     = (const float*)d_in[14];
    const float* ln_b     = (const float*)d_in[15];
    const float* out_w1   = (const float*)d_in[16];
    const float* out_b1   = (const float*)d_in[17];
    const float* out_w2   = (const float*)d_in[18];
    const float* out_b2   = (const float*)d_in[19];
    const float* out_w3   = (const float*)d_in[20];
    const float* out_b3   = (const float*)d_in[21];
    float* out = (float*)d_out;

    float *x, *aggr, *pool, *gcnt;
    __half *xh, *eh, *xw;
    uint2 *w0p, *w1p, *w2p, *ewp;
    int *deg, *cur, *off, *bsum, *pos, *srcs, *dsts;
    cudaGetSymbolAddress((void**)&x,    g_x);
    cudaGetSymbolAddress((void**)&xh,   g_xh);
    cudaGetSymbolAddress((void**)&eh,   g_eh);
    cudaGetSymbolAddress((void**)&xw,   g_xw);
    cudaGetSymbolAddress((void**)&aggr, g_aggr);
    cudaGetSymbolAddress((void**)&pool, g_pool);
    cudaGetSymbolAddress((void**)&gcnt, g_gcnt);
    cudaGetSymbolAddress((void**)&w0p,  g_w0p);
    cudaGetSymbolAddress((void**)&w1p,  g_w1p);
    cudaGetSymbolAddress((void**)&w2p,  g_w2p);
    cudaGetSymbolAddress((void**)&ewp,  g_ewp);
    cudaGetSymbolAddress((void**)&deg,  g_deg);
    cudaGetSymbolAddress((void**)&cur,  g_cur);
    cudaGetSymbolAddress((void**)&off,  g_off);
    cudaGetSymbolAddress((void**)&bsum, g_bsum);
    cudaGetSymbolAddress((void**)&pos,  g_pos);
    cudaGetSymbolAddress((void**)&srcs, g_srcs);
    cudaGetSymbolAddress((void**)&dsts, g_dsts);

    static int attr_set = 0;
    static cudaStream_t s1;
    static cudaEvent_t evRoot, evNode, evJoin;
    if (!attr_set) {
        cudaFuncSetAttribute(k_xw,
                             cudaFuncAttributeMaxDynamicSharedMemorySize, XW_SMEM);
        cudaFuncSetAttribute(k_xw_ln,
                             cudaFuncAttributeMaxDynamicSharedMemorySize, XW_SMEM);
        cudaStreamCreateWithFlags(&s1, cudaStreamNonBlocking);
        cudaEventCreateWithFlags(&evRoot, cudaEventDisableTiming);
        cudaEventCreateWithFlags(&evNode, cudaEventDisableTiming);
        cudaEventCreateWithFlags(&evJoin, cudaEventDisableTiming);
        attr_set = 1;
    }

    // ---- fork: chain A (node side) on s1, chain B (edge side) on stream 0 ----
    cudaEventRecord(evRoot, 0);
    cudaStreamWaitEvent(s1, evRoot, 0);

    // chain A (s1): node embed, weight packing, aggr/pool/gcnt zero, layer-0 XW
    cudaMemsetAsync(aggr, 0, N_NODES * 128 * sizeof(float), s1);
    cudaMemsetAsync(pool, 0, N_GRAPHS * 128 * sizeof(float), s1);
    cudaMemsetAsync(gcnt, 0, N_GRAPHS * sizeof(float), s1);
    k_node_embed<<<N_NODES / 4, 128, 0, s1>>>(atom_fea, emb_w, emb_b,
                                              emb_ln_g, emb_ln_b, x, xh);
    k_cvt<<<ceildiv(NLAYERS * 8192, 256), 256, 0, s1>>>(conv_w1, conv_w2, edge_w,
                                                        w0p, w1p, w2p, ewp);
    cudaEventRecord(evNode, s1);   // ewp ready (needed by edge_embed on stream 0)
    k_xw<<<ceildiv(N_NODES, 128), 512, XW_SMEM, s1>>>(xh, w0p, conv_b1, xw);
    cudaEventRecord(evJoin, s1);   // xw + aggr/pool/gcnt ready

    // chain B (stream 0): degree, scan, scatter, edge embedding
    cudaMemsetAsync(deg,  0, N_NODES * sizeof(int), 0);
    cudaMemsetAsync(cur,  0, N_NODES * sizeof(int), 0);
    k_deg<<<ceildiv(N_EDGES, 256), 256>>>(nbr_idx, deg, N_EDGES);
    k_scan1<<<SCAN_NB, 512>>>(deg, bsum);
    k_scan2<<<1, 128>>>(bsum);
    k_scan3<<<SCAN_NB, 512>>>(deg, bsum, off);
    k_scatter<<<ceildiv(N_EDGES, 256), 256>>>(nbr_idx, off, cur, pos, srcs, dsts);
    cudaStreamWaitEvent(0, evNode, 0);   // ewp ready
    k_edge_embed<<<N_EDGES / 64, 256>>>(nbr_fea, ewp, edge_b, pos, eh);
    cudaStreamWaitEvent(0, evJoin, 0);   // xw(0), aggr/pool/gcnt ready

    for (int i = 0; i < NLAYERS; i++) {
        const float* b1 = conv_b1 + (long)i * 256;
        const float* b2 = conv_b2 + (long)i * 128;

        if (i > 0)
            k_xw_ln<<<ceildiv(N_NODES, 128), 512, XW_SMEM>>>(
                ln_g + (i - 1) * 128, ln_b + (i - 1) * 128, deg, x, aggr,
                w0p + (long)i * 8192, b1, xw);
        k_conv<<<N_UNITS, 256, CONV_SMEM>>>(eh, w1p + (long)i * 8192,
                                            w2p + (long)i * 8192, xw, b2,
                                            srcs, dsts, aggr);
    }
    k_pool_ln<<<ceildiv(N_NODES, 4), 128>>>(x, aggr, deg,
                                            ln_g + 4 * 128, ln_b + 4 * 128,
                                            batch, pool, gcnt);

    k_head<<<N_GRAPHS, 128>>>(pool, gcnt, out_w1, out_b1, out_w2, out_b2,
                              out_w3, out_b3, out);
    (void)in_sizes; (void)n_in; (void)out_size;
}